// round 1
// baseline (speedup 1.0000x reference)
#include <cuda_runtime.h>
#include <cstdint>

#define T_LEN 8192
#define VOCAB 128000
#define EMB 10
#define HID 10
#define CDIM 20
#define NCHUNK 128
#define CHL 64            // NCHUNK * CHL == T_LEN

#define TPB 128
#define PP 4                               // row-pairs per thread
#define ROWS_PER_CTA (TPB * 2 * PP)        // 1024
#define VSLABS (VOCAB / ROWS_PER_CTA)      // 125
#define TSLABS 16
#define TT (T_LEN / TSLABS)                // 512
#define TILE 256                           // t per smem tile

// ---- scratch (device globals; no allocation allowed) ----
__device__ float g_comb[T_LEN * CDIM];     // [w_t (10) | h_t (10)] per step
__device__ float g_e[T_LEN * HID];         // e_t = B*w_t + b_i2h
__device__ float g_v[NCHUNK * HID];        // per-chunk scan partials
__device__ float g_hs[NCHUNK * HID];       // per-chunk entry hidden states
__device__ unsigned long long g_best[T_LEN];

// ---- packed f32x2 helpers ----
__device__ __forceinline__ unsigned long long ffma2(unsigned long long a,
                                                    unsigned long long b,
                                                    unsigned long long c) {
  unsigned long long d;
  asm("fma.rn.f32x2 %0, %1, %2, %3;" : "=l"(d) : "l"(a), "l"(b), "l"(c));
  return d;
}
__device__ __forceinline__ unsigned long long pack2(unsigned int lo, unsigned int hi) {
  unsigned long long d;
  asm("mov.b64 %0, {%1, %2};" : "=l"(d) : "r"(lo), "r"(hi));
  return d;
}
__device__ __forceinline__ void unpack2(unsigned long long v, unsigned int& lo, unsigned int& hi) {
  asm("mov.b64 {%0, %1}, %2;" : "=r"(lo), "=r"(hi) : "l"(v));
}

// ============================================================================
// K0: embeddings -> combined[:,0:10], e_t = B*w_t + b_i2h, init g_best
// ============================================================================
__global__ void k0_embed(const int* __restrict__ ib, const float* __restrict__ emb,
                         const float* __restrict__ Wih, const float* __restrict__ bih) {
  int t = blockIdx.x * blockDim.x + threadIdx.x;
  if (t >= T_LEN) return;
  int ix = ib[t];
  float w[EMB];
#pragma unroll
  for (int k = 0; k < EMB; k++) {
    w[k] = emb[ix * EMB + k];
    g_comb[t * CDIM + k] = w[k];
  }
#pragma unroll
  for (int i = 0; i < HID; i++) {
    float s = bih[i];
#pragma unroll
    for (int k = 0; k < EMB; k++) s += Wih[i * CDIM + k] * w[k];
    g_e[t * HID + i] = s;
  }
  g_best[t] = 0ULL;
}

// ============================================================================
// K1: per-chunk partial scan from h=0 (chunks in parallel, 1 thread each)
// ============================================================================
__global__ void k1_chunkv(const float* __restrict__ Wih) {
  int c = threadIdx.x;  // 0..NCHUNK-1
  float A[HID][HID];
#pragma unroll
  for (int i = 0; i < HID; i++)
#pragma unroll
    for (int k = 0; k < HID; k++) A[i][k] = Wih[i * CDIM + EMB + k];
  float h[HID];
#pragma unroll
  for (int i = 0; i < HID; i++) h[i] = 0.f;
  const float* e = &g_e[c * CHL * HID];
  for (int j = 0; j < CHL; j++) {
    float hn[HID];
#pragma unroll
    for (int i = 0; i < HID; i++) {
      float s = e[j * HID + i];
#pragma unroll
      for (int k = 0; k < HID; k++) s += A[i][k] * h[k];
      hn[i] = s;
    }
#pragma unroll
    for (int i = 0; i < HID; i++) h[i] = hn[i];
  }
#pragma unroll
  for (int i = 0; i < HID; i++) g_v[c * HID + i] = h[i];
}

// ============================================================================
// K2: M = A^CHL (6 squarings, CHL=64), then serial chunk-level scan -> g_hs
// ============================================================================
__global__ void k2_scan(const float* __restrict__ Wih) {
  __shared__ float sM[HID * HID], sT[HID * HID], sh[HID], shn[HID];
  int tid = threadIdx.x;
  if (tid < 100) sM[tid] = Wih[(tid / 10) * CDIM + EMB + (tid % 10)];
  __syncthreads();
  for (int s = 0; s < 6; s++) {   // 2^6 = 64 = CHL
    float acc = 0.f;
    if (tid < 100) {
      int i = tid / 10, k = tid % 10;
#pragma unroll
      for (int j = 0; j < 10; j++) acc += sM[i * 10 + j] * sM[j * 10 + k];
    }
    __syncthreads();
    if (tid < 100) sT[tid] = acc;
    __syncthreads();
    if (tid < 100) sM[tid] = sT[tid];
    __syncthreads();
  }
  if (tid < HID) sh[tid] = 0.f;
  __syncthreads();
  for (int c = 0; c < NCHUNK; c++) {
    if (tid < HID) {
      g_hs[c * HID + tid] = sh[tid];
      float hn = g_v[c * HID + tid];
#pragma unroll
      for (int k = 0; k < HID; k++) hn += sM[tid * 10 + k] * sh[k];
      shn[tid] = hn;
    }
    __syncthreads();
    if (tid < HID) sh[tid] = shn[tid];
    __syncthreads();
  }
}

// ============================================================================
// K3: replay each chunk from its entry state; write h_t -> combined[:,10:20]
// ============================================================================
__global__ void k3_fill(const float* __restrict__ Wih) {
  int c = threadIdx.x;
  float A[HID][HID];
#pragma unroll
  for (int i = 0; i < HID; i++)
#pragma unroll
    for (int k = 0; k < HID; k++) A[i][k] = Wih[i * CDIM + EMB + k];
  float h[HID];
#pragma unroll
  for (int i = 0; i < HID; i++) h[i] = g_hs[c * HID + i];
  const float* e = &g_e[c * CHL * HID];
  float* cb = &g_comb[c * CHL * CDIM];
  for (int j = 0; j < CHL; j++) {
#pragma unroll
    for (int i = 0; i < HID; i++) cb[j * CDIM + EMB + i] = h[i];
    float hn[HID];
#pragma unroll
    for (int i = 0; i < HID; i++) {
      float s = e[j * HID + i];
#pragma unroll
      for (int k = 0; k < HID; k++) s += A[i][k] * h[k];
      hn[i] = s;
    }
#pragma unroll
    for (int i = 0; i < HID; i++) h[i] = hn[i];
  }
}

// ============================================================================
// K5: fused logits-GEMM + argmax. FFMA2 (f32x2), weights register-resident,
//     combined staged duplicated in smem, per-t warp reduce + atomicMax.
// ============================================================================
__global__ void __launch_bounds__(TPB, 2)
k5_argmax(const float* __restrict__ Wio, const float* __restrict__ bio) {
  __shared__ unsigned long long sc[TILE * CDIM];  // 40 KB, (c_k, c_k) duplicated
  int vslab = blockIdx.x % VSLABS;
  int tslab = blockIdx.x / VSLABS;
  int tid = threadIdx.x;
  int rbase = vslab * ROWS_PER_CTA + tid * (2 * PP);

  unsigned long long w2[PP][CDIM], b2[PP];
#pragma unroll
  for (int p = 0; p < PP; p++) {
    const float* r0 = &Wio[(rbase + 2 * p) * CDIM];
    const float* r1 = r0 + CDIM;
#pragma unroll
    for (int k = 0; k < CDIM; k++)
      w2[p][k] = pack2(__float_as_uint(r0[k]), __float_as_uint(r1[k]));
    b2[p] = pack2(__float_as_uint(bio[rbase + 2 * p]),
                  __float_as_uint(bio[rbase + 2 * p + 1]));
  }

  int t0 = tslab * TT;
  for (int tile = 0; tile < TT; tile += TILE) {
    __syncthreads();
    const float* src = &g_comb[(t0 + tile) * CDIM];
    for (int i = tid; i < TILE * CDIM; i += TPB) {
      unsigned int u = __float_as_uint(src[i]);
      sc[i] = pack2(u, u);
    }
    __syncthreads();

    for (int j = 0; j < TILE; j++) {
      const unsigned long long* cp = &sc[j * CDIM];
      unsigned long long acc[PP];
#pragma unroll
      for (int p = 0; p < PP; p++) acc[p] = b2[p];

      unsigned long long creg[EMB];
      // first half of c (w part)
#pragma unroll
      for (int k = 0; k < EMB; k++) creg[k] = cp[k];
#pragma unroll
      for (int k = 0; k < EMB; k++) {
#pragma unroll
        for (int p = 0; p < PP; p++) acc[p] = ffma2(w2[p][k], creg[k], acc[p]);
      }
      // second half of c (h part)
#pragma unroll
      for (int k = 0; k < EMB; k++) creg[k] = cp[EMB + k];
#pragma unroll
      for (int k = 0; k < EMB; k++) {
#pragma unroll
        for (int p = 0; p < PP; p++) acc[p] = ffma2(w2[p][EMB + k], creg[k], acc[p]);
      }

      // local argmax via order-preserving integer keys (ALU pipe, not FMA)
      unsigned int bkey = 0u;
      int bidx = 0;
#pragma unroll
      for (int p = 0; p < PP; p++) {
        unsigned int lo, hi;
        unpack2(acc[p], lo, hi);
        unsigned int k0 = lo ^ ((unsigned int)((int)lo >> 31) | 0x80000000u);
        unsigned int k1 = hi ^ ((unsigned int)((int)hi >> 31) | 0x80000000u);
        if (k0 > bkey) { bkey = k0; bidx = rbase + 2 * p; }
        if (k1 > bkey) { bkey = k1; bidx = rbase + 2 * p + 1; }
      }
      // pack: key high, ~idx low  (ties -> smallest index wins, like jnp.argmax)
      unsigned long long packed =
          ((unsigned long long)bkey << 32) | (unsigned int)(~(unsigned int)bidx);
#pragma unroll
      for (int off = 16; off; off >>= 1) {
        unsigned long long o = __shfl_down_sync(0xffffffffu, packed, off);
        if (o > packed) packed = o;
      }
      if ((tid & 31) == 0) atomicMax(&g_best[t0 + tile + j], packed);
    }
  }
}

// ============================================================================
// K6: decode packed (key, ~idx) -> float index
// ============================================================================
__global__ void k6_out(float* __restrict__ out) {
  int t = blockIdx.x * blockDim.x + threadIdx.x;
  if (t < T_LEN) out[t] = (float)(~(unsigned int)g_best[t]);
}

extern "C" void kernel_launch(void* const* d_in, const int* in_sizes, int n_in,
                              void* d_out, int out_size) {
  const int*   ib  = (const int*)d_in[0];
  const float* emb = (const float*)d_in[1];
  const float* Wih = (const float*)d_in[2];
  const float* bih = (const float*)d_in[3];
  const float* Wio = (const float*)d_in[4];
  const float* bio = (const float*)d_in[5];
  float* out = (float*)d_out;

  k0_embed<<<T_LEN / 128, 128>>>(ib, emb, Wih, bih);
  k1_chunkv<<<1, NCHUNK>>>(Wih);
  k2_scan<<<1, 128>>>(Wih);
  k3_fill<<<1, NCHUNK>>>(Wih);
  k5_argmax<<<VSLABS * TSLABS, TPB>>>(Wio, bio);
  k6_out<<<T_LEN / 128, 128>>>(out);
}

// round 2
// speedup vs baseline: 1.3182x; 1.3182x over previous
#include <cuda_runtime.h>
#include <cstdint>

#define T_LEN 8192
#define VOCAB 128000
#define EMB 10
#define HID 10
#define CDIM 20
#define NCHUNK 256
#define CHL 32            // NCHUNK * CHL == T_LEN

#define TPB 128
#define PP 4                               // row-pairs per thread
#define ROWS_PER_CTA (TPB * 2 * PP)        // 1024
#define VSLABS (VOCAB / ROWS_PER_CTA)      // 125
#define TSLABS 16
#define TT (T_LEN / TSLABS)                // 512
#define TILE 256                           // t per smem tile

// ---- scratch (device globals; no allocation allowed) ----
__device__ float g_comb[T_LEN * CDIM];       // [w_t (10) | h_t (10)] per step, t-major
__device__ float g_ecm[T_LEN * HID];         // e in chunk-major [j][c][i]
__device__ float g_hcm[T_LEN * HID];         // h in chunk-major [j][c][i]
__device__ float g_v[NCHUNK * HID];          // per-chunk scan partials
__device__ float g_hs[NCHUNK * HID];         // per-chunk entry hidden states
__device__ unsigned long long g_best[T_LEN];

// ---- packed f32x2 helpers ----
__device__ __forceinline__ unsigned long long ffma2(unsigned long long a,
                                                    unsigned long long b,
                                                    unsigned long long c) {
  unsigned long long d;
  asm("fma.rn.f32x2 %0, %1, %2, %3;" : "=l"(d) : "l"(a), "l"(b), "l"(c));
  return d;
}
__device__ __forceinline__ unsigned long long pack2(unsigned int lo, unsigned int hi) {
  unsigned long long d;
  asm("mov.b64 %0, {%1, %2};" : "=l"(d) : "r"(lo), "r"(hi));
  return d;
}
__device__ __forceinline__ void unpack2(unsigned long long v, unsigned int& lo, unsigned int& hi) {
  asm("mov.b64 {%0, %1}, %2;" : "=r"(lo), "=r"(hi) : "l"(v));
}

// ============================================================================
// K0: embeddings -> combined[:,0:10] (t-major), e_t -> chunk-major, init g_best
// ============================================================================
__global__ void k0_embed(const int* __restrict__ ib, const float* __restrict__ emb,
                         const float* __restrict__ Wih, const float* __restrict__ bih) {
  int t = blockIdx.x * blockDim.x + threadIdx.x;
  if (t >= T_LEN) return;
  int ix = ib[t];
  float w[EMB];
#pragma unroll
  for (int k = 0; k < EMB; k++) {
    w[k] = emb[ix * EMB + k];
    g_comb[t * CDIM + k] = w[k];
  }
  int c = t / CHL, j = t % CHL;
  float* e = &g_ecm[(j * NCHUNK + c) * HID];
#pragma unroll
  for (int i = 0; i < HID; i++) {
    float s = bih[i];
#pragma unroll
    for (int k = 0; k < EMB; k++) s += Wih[i * CDIM + k] * w[k];
    e[i] = s;
  }
  g_best[t] = 0ULL;
}

// ============================================================================
// K1: per-chunk partial scan from h=0 (coalesced chunk-major loads)
// ============================================================================
__global__ void k1_chunkv(const float* __restrict__ Wih) {
  int c = blockIdx.x * blockDim.x + threadIdx.x;  // 0..NCHUNK-1
  float A[HID][HID];
#pragma unroll
  for (int i = 0; i < HID; i++)
#pragma unroll
    for (int k = 0; k < HID; k++) A[i][k] = Wih[i * CDIM + EMB + k];
  float h[HID];
#pragma unroll
  for (int i = 0; i < HID; i++) h[i] = 0.f;
  for (int j = 0; j < CHL; j++) {
    const float* e = &g_ecm[(j * NCHUNK + c) * HID];
    float hn[HID];
#pragma unroll
    for (int i = 0; i < HID; i++) {
      float s = e[i];
#pragma unroll
      for (int k = 0; k < HID; k++) s += A[i][k] * h[k];
      hn[i] = s;
    }
#pragma unroll
    for (int i = 0; i < HID; i++) h[i] = hn[i];
  }
#pragma unroll
  for (int i = 0; i < HID; i++) g_v[c * HID + i] = h[i];
}

// ============================================================================
// K2: M = A^CHL (5 squarings, CHL=32), then serial chunk-level scan -> g_hs
// ============================================================================
__global__ void k2_scan(const float* __restrict__ Wih) {
  __shared__ float sM[HID * HID], sT[HID * HID], sh[HID], shn[HID];
  int tid = threadIdx.x;
  if (tid < 100) sM[tid] = Wih[(tid / 10) * CDIM + EMB + (tid % 10)];
  __syncthreads();
  for (int s = 0; s < 5; s++) {   // 2^5 = 32 = CHL
    float acc = 0.f;
    if (tid < 100) {
      int i = tid / 10, k = tid % 10;
#pragma unroll
      for (int j = 0; j < 10; j++) acc += sM[i * 10 + j] * sM[j * 10 + k];
    }
    __syncthreads();
    if (tid < 100) sT[tid] = acc;
    __syncthreads();
    if (tid < 100) sM[tid] = sT[tid];
    __syncthreads();
  }
  if (tid < HID) sh[tid] = 0.f;
  __syncthreads();
  for (int c = 0; c < NCHUNK; c++) {
    if (tid < HID) {
      g_hs[c * HID + tid] = sh[tid];
      float hn = g_v[c * HID + tid];
#pragma unroll
      for (int k = 0; k < HID; k++) hn += sM[tid * 10 + k] * sh[k];
      shn[tid] = hn;
    }
    __syncthreads();
    if (tid < HID) sh[tid] = shn[tid];
    __syncthreads();
  }
}

// ============================================================================
// K3: replay each chunk from its entry state; h -> chunk-major (coalesced)
// ============================================================================
__global__ void k3_fill(const float* __restrict__ Wih) {
  int c = blockIdx.x * blockDim.x + threadIdx.x;
  float A[HID][HID];
#pragma unroll
  for (int i = 0; i < HID; i++)
#pragma unroll
    for (int k = 0; k < HID; k++) A[i][k] = Wih[i * CDIM + EMB + k];
  float h[HID];
#pragma unroll
  for (int i = 0; i < HID; i++) h[i] = g_hs[c * HID + i];
  for (int j = 0; j < CHL; j++) {
    const float* e = &g_ecm[(j * NCHUNK + c) * HID];
    float* ho = &g_hcm[(j * NCHUNK + c) * HID];
    float hn[HID];
#pragma unroll
    for (int i = 0; i < HID; i++) {
      ho[i] = h[i];
      float s = e[i];
#pragma unroll
      for (int k = 0; k < HID; k++) s += A[i][k] * h[k];
      hn[i] = s;
    }
#pragma unroll
    for (int i = 0; i < HID; i++) h[i] = hn[i];
  }
}

// ============================================================================
// K4: transpose h chunk-major -> g_comb[:,10:20] (coalesced read, parallel)
// ============================================================================
__global__ void k4_transpose() {
  int idx = blockIdx.x * blockDim.x + threadIdx.x;   // over T_LEN*HID
  if (idx >= T_LEN * HID) return;
  int j = idx / (NCHUNK * HID);
  int r = idx % (NCHUNK * HID);
  int c = r / HID, i = r % HID;
  int t = c * CHL + j;
  g_comb[t * CDIM + EMB + i] = g_hcm[idx];
}

// ============================================================================
// K5: fused logits-GEMM + argmax. FFMA2, register weights, smem combined,
//     REDUX warp argmax + single-lane atomicMax.
// ============================================================================
__global__ void __launch_bounds__(TPB, 2)
k5_argmax(const float* __restrict__ Wio, const float* __restrict__ bio) {
  __shared__ __align__(16) unsigned long long sc[TILE * CDIM];  // 40 KB
  int vslab = blockIdx.x % VSLABS;
  int tslab = blockIdx.x / VSLABS;
  int tid = threadIdx.x;
  int lane = tid & 31;
  int rbase = vslab * ROWS_PER_CTA + tid * (2 * PP);

  unsigned long long w2[PP][CDIM], b2[PP];
#pragma unroll
  for (int p = 0; p < PP; p++) {
    const float* r0 = &Wio[(rbase + 2 * p) * CDIM];
    const float* r1 = r0 + CDIM;
#pragma unroll
    for (int k = 0; k < CDIM; k++)
      w2[p][k] = pack2(__float_as_uint(r0[k]), __float_as_uint(r1[k]));
    b2[p] = pack2(__float_as_uint(bio[rbase + 2 * p]),
                  __float_as_uint(bio[rbase + 2 * p + 1]));
  }

  int t0 = tslab * TT;
  for (int tile = 0; tile < TT; tile += TILE) {
    __syncthreads();
    const float* src = &g_comb[(t0 + tile) * CDIM];
    for (int i = tid; i < TILE * CDIM; i += TPB) {
      unsigned int u = __float_as_uint(src[i]);
      sc[i] = pack2(u, u);
    }
    __syncthreads();

#pragma unroll 2
    for (int j = 0; j < TILE; j++) {
      const ulonglong2* cp = reinterpret_cast<const ulonglong2*>(&sc[j * CDIM]);
      unsigned long long acc[PP];
#pragma unroll
      for (int p = 0; p < PP; p++) acc[p] = b2[p];

#pragma unroll
      for (int k2i = 0; k2i < CDIM / 2; k2i++) {
        ulonglong2 cv = cp[k2i];
#pragma unroll
        for (int p = 0; p < PP; p++) acc[p] = ffma2(w2[p][2 * k2i], cv.x, acc[p]);
#pragma unroll
        for (int p = 0; p < PP; p++) acc[p] = ffma2(w2[p][2 * k2i + 1], cv.y, acc[p]);
      }

      // thread-local argmax, order-preserving integer keys (ALU pipe)
      unsigned int bkey = 0u;
      int bidx = 0;
#pragma unroll
      for (int p = 0; p < PP; p++) {
        unsigned int lo, hi;
        unpack2(acc[p], lo, hi);
        unsigned int k0 = lo ^ ((unsigned int)((int)lo >> 31) | 0x80000000u);
        unsigned int k1 = hi ^ ((unsigned int)((int)hi >> 31) | 0x80000000u);
        if (k0 > bkey) { bkey = k0; bidx = rbase + 2 * p; }
        if (k1 > bkey) { bkey = k1; bidx = rbase + 2 * p + 1; }
      }
      // warp argmax: REDUX + ballot; lowest lane == smallest vocab index
      unsigned int m = __reduce_max_sync(0xffffffffu, bkey);
      unsigned int bal = __ballot_sync(0xffffffffu, bkey == m);
      if (lane == __ffs(bal) - 1) {
        unsigned long long packed =
            ((unsigned long long)m << 32) | (unsigned int)(~(unsigned int)bidx);
        atomicMax(&g_best[t0 + tile + j], packed);
      }
    }
  }
}

// ============================================================================
// K6: decode packed (key, ~idx) -> float index
// ============================================================================
__global__ void k6_out(float* __restrict__ out) {
  int t = blockIdx.x * blockDim.x + threadIdx.x;
  if (t < T_LEN) out[t] = (float)(~(unsigned int)g_best[t]);
}

extern "C" void kernel_launch(void* const* d_in, const int* in_sizes, int n_in,
                              void* d_out, int out_size) {
  const int*   ib  = (const int*)d_in[0];
  const float* emb = (const float*)d_in[1];
  const float* Wih = (const float*)d_in[2];
  const float* bih = (const float*)d_in[3];
  const float* Wio = (const float*)d_in[4];
  const float* bio = (const float*)d_in[5];
  float* out = (float*)d_out;

  k0_embed<<<T_LEN / 128, 128>>>(ib, emb, Wih, bih);
  k1_chunkv<<<NCHUNK / 128, 128>>>(Wih);
  k2_scan<<<1, 128>>>(Wih);
  k3_fill<<<NCHUNK / 128, 128>>>(Wih);
  k4_transpose<<<(T_LEN * HID + 127) / 128, 128>>>();
  k5_argmax<<<VSLABS * TSLABS, TPB>>>(Wio, bio);
  k6_out<<<T_LEN / 128, 128>>>(out);
}

// round 3
// speedup vs baseline: 1.4020x; 1.0635x over previous
#include <cuda_runtime.h>
#include <cstdint>

#define T_LEN 8192
#define VOCAB 128000
#define EMB 10
#define HID 10
#define CDIM 20
#define NCHUNK 1024
#define CHL 8             // NCHUNK * CHL == T_LEN
#define NGRP 32           // two-level scan: 32 groups of 32 chunks

#define TPB 128
#define PP 4                               // row-pairs per thread
#define ROWS_PER_CTA (TPB * 2 * PP)        // 1024
#define VSLABS (VOCAB / ROWS_PER_CTA)      // 125
#define TSLABS 16
#define TT (T_LEN / TSLABS)                // 512
#define TILE 256                           // t per smem tile

// ---- scratch (device globals; no allocation allowed) ----
__device__ float g_comb[T_LEN * CDIM];       // [w_t (10) | h_t (10)] per step, t-major
__device__ float g_ecm[T_LEN * HID];         // e in chunk-major [j][c][i]
__device__ float g_hcm[T_LEN * HID];         // h in chunk-major [j][c][i]
__device__ float g_v[NCHUNK * HID];          // per-chunk scan partials
__device__ float g_hs[NCHUNK * HID];         // per-chunk entry hidden states
__device__ unsigned long long g_best[T_LEN];

// ---- packed f32x2 helpers ----
__device__ __forceinline__ unsigned long long ffma2(unsigned long long a,
                                                    unsigned long long b,
                                                    unsigned long long c) {
  unsigned long long d;
  asm("fma.rn.f32x2 %0, %1, %2, %3;" : "=l"(d) : "l"(a), "l"(b), "l"(c));
  return d;
}
__device__ __forceinline__ unsigned long long pack2(unsigned int lo, unsigned int hi) {
  unsigned long long d;
  asm("mov.b64 %0, {%1, %2};" : "=l"(d) : "r"(lo), "r"(hi));
  return d;
}
__device__ __forceinline__ void unpack2f(unsigned long long v, float& lo, float& hi) {
  unsigned int a, b;
  asm("mov.b64 {%0, %1}, %2;" : "=r"(a), "=r"(b) : "l"(v));
  lo = __uint_as_float(a);
  hi = __uint_as_float(b);
}
__device__ __forceinline__ unsigned int okey(float f) {
  unsigned int u = __float_as_uint(f);
  return u ^ ((unsigned int)((int)u >> 31) | 0x80000000u);
}

// ============================================================================
// K0: embeddings -> combined[:,0:10] (t-major), e_t -> chunk-major, init g_best
// ============================================================================
__global__ void k0_embed(const int* __restrict__ ib, const float* __restrict__ emb,
                         const float* __restrict__ Wih, const float* __restrict__ bih) {
  int t = blockIdx.x * blockDim.x + threadIdx.x;
  if (t >= T_LEN) return;
  int ix = ib[t];
  float w[EMB];
#pragma unroll
  for (int k = 0; k < EMB; k++) {
    w[k] = emb[ix * EMB + k];
    g_comb[t * CDIM + k] = w[k];
  }
  int c = t / CHL, j = t % CHL;
  float* e = &g_ecm[(j * NCHUNK + c) * HID];
#pragma unroll
  for (int i = 0; i < HID; i++) {
    float s = bih[i];
#pragma unroll
    for (int k = 0; k < EMB; k++) s += Wih[i * CDIM + k] * w[k];
    e[i] = s;
  }
  g_best[t] = 0ULL;
}

// ============================================================================
// K1: per-chunk partial scan from h=0 (CHL=8 serial mat-vecs, coalesced)
// ============================================================================
__global__ void k1_chunkv(const float* __restrict__ Wih) {
  int c = blockIdx.x * blockDim.x + threadIdx.x;  // 0..NCHUNK-1
  float A[HID][HID];
#pragma unroll
  for (int i = 0; i < HID; i++)
#pragma unroll
    for (int k = 0; k < HID; k++) A[i][k] = Wih[i * CDIM + EMB + k];
  float h[HID];
#pragma unroll
  for (int i = 0; i < HID; i++) h[i] = 0.f;
#pragma unroll
  for (int j = 0; j < CHL; j++) {
    const float* e = &g_ecm[(j * NCHUNK + c) * HID];
    float hn[HID];
#pragma unroll
    for (int i = 0; i < HID; i++) {
      float s = e[i];
#pragma unroll
      for (int k = 0; k < HID; k++) s += A[i][k] * h[k];
      hn[i] = s;
    }
#pragma unroll
    for (int i = 0; i < HID; i++) h[i] = hn[i];
  }
#pragma unroll
  for (int i = 0; i < HID; i++) g_v[c * HID + i] = h[i];
}

// ============================================================================
// K2: two-level chunk scan. M8=A^8 (3 sq), M256=M8^32 (5 sq).
//     Phase1: 32 parallel group partials. Phase2: serial over 32 groups.
//     Phase3: 32 parallel replays -> g_hs entry states.
// ============================================================================
__global__ void k2_scan(const float* __restrict__ Wih) {
  __shared__ float sM8[100], sM256[100], sT[100];
  __shared__ float sV[NCHUNK * 11];        // padded stride-11, [c*32+g] layout
  __shared__ float sgp[NGRP * 10], sge[NGRP * 10];
  int tid = threadIdx.x;  // 128 threads

  if (tid < 100) sM8[tid] = Wih[(tid / 10) * CDIM + EMB + (tid % 10)];
  __syncthreads();
  // A^8: 3 squarings
  for (int s = 0; s < 3; s++) {
    float acc = 0.f;
    if (tid < 100) {
      int i = tid / 10, k = tid % 10;
#pragma unroll
      for (int j = 0; j < 10; j++) acc += sM8[i * 10 + j] * sM8[j * 10 + k];
    }
    __syncthreads();
    if (tid < 100) sT[tid] = acc;
    __syncthreads();
    if (tid < 100) sM8[tid] = sT[tid];
    __syncthreads();
  }
  if (tid < 100) sM256[tid] = sM8[tid];
  __syncthreads();
  // (A^8)^32: 5 squarings
  for (int s = 0; s < 5; s++) {
    float acc = 0.f;
    if (tid < 100) {
      int i = tid / 10, k = tid % 10;
#pragma unroll
      for (int j = 0; j < 10; j++) acc += sM256[i * 10 + j] * sM256[j * 10 + k];
    }
    __syncthreads();
    if (tid < 100) sT[tid] = acc;
    __syncthreads();
    if (tid < 100) sM256[tid] = sT[tid];
    __syncthreads();
  }
  // stage g_v transposed: chunk ch = g*32 + c  ->  sV[(c*32+g)*11 + i]
  for (int idx = tid; idx < NCHUNK * HID; idx += blockDim.x) {
    int ch = idx / HID, i = idx % HID;
    int g = ch / 32, c = ch % 32;
    sV[(c * 32 + g) * 11 + i] = g_v[idx];
  }
  __syncthreads();
  // Phase 1: group partials (thread g scans 32 chunks from 0)
  if (tid < NGRP) {
    float h[HID];
#pragma unroll
    for (int i = 0; i < HID; i++) h[i] = 0.f;
    for (int c = 0; c < 32; c++) {
      const float* v = &sV[(c * 32 + tid) * 11];
      float hn[HID];
#pragma unroll
      for (int i = 0; i < HID; i++) {
        float s = v[i];
#pragma unroll
        for (int k = 0; k < HID; k++) s += sM8[i * 10 + k] * h[k];
        hn[i] = s;
      }
#pragma unroll
      for (int i = 0; i < HID; i++) h[i] = hn[i];
    }
#pragma unroll
    for (int i = 0; i < HID; i++) sgp[tid * 10 + i] = h[i];
  }
  __syncthreads();
  // Phase 2: serial scan over 32 groups with M256
  if (tid == 0) {
    float h[HID];
#pragma unroll
    for (int i = 0; i < HID; i++) h[i] = 0.f;
    for (int g = 0; g < NGRP; g++) {
#pragma unroll
      for (int i = 0; i < HID; i++) sge[g * 10 + i] = h[i];
      float hn[HID];
#pragma unroll
      for (int i = 0; i < HID; i++) {
        float s = sgp[g * 10 + i];
#pragma unroll
        for (int k = 0; k < HID; k++) s += sM256[i * 10 + k] * h[k];
        hn[i] = s;
      }
#pragma unroll
      for (int i = 0; i < HID; i++) h[i] = hn[i];
    }
  }
  __syncthreads();
  // Phase 3: replay each group -> chunk entry states g_hs
  if (tid < NGRP) {
    float h[HID];
#pragma unroll
    for (int i = 0; i < HID; i++) h[i] = sge[tid * 10 + i];
    for (int c = 0; c < 32; c++) {
      int ch = tid * 32 + c;
#pragma unroll
      for (int i = 0; i < HID; i++) g_hs[ch * HID + i] = h[i];
      const float* v = &sV[(c * 32 + tid) * 11];
      float hn[HID];
#pragma unroll
      for (int i = 0; i < HID; i++) {
        float s = v[i];
#pragma unroll
        for (int k = 0; k < HID; k++) s += sM8[i * 10 + k] * h[k];
        hn[i] = s;
      }
#pragma unroll
      for (int i = 0; i < HID; i++) h[i] = hn[i];
    }
  }
}

// ============================================================================
// K3: replay each chunk from its entry state; h -> chunk-major (coalesced)
// ============================================================================
__global__ void k3_fill(const float* __restrict__ Wih) {
  int c = blockIdx.x * blockDim.x + threadIdx.x;
  float A[HID][HID];
#pragma unroll
  for (int i = 0; i < HID; i++)
#pragma unroll
    for (int k = 0; k < HID; k++) A[i][k] = Wih[i * CDIM + EMB + k];
  float h[HID];
#pragma unroll
  for (int i = 0; i < HID; i++) h[i] = g_hs[c * HID + i];
#pragma unroll
  for (int j = 0; j < CHL; j++) {
    const float* e = &g_ecm[(j * NCHUNK + c) * HID];
    float* ho = &g_hcm[(j * NCHUNK + c) * HID];
    float hn[HID];
#pragma unroll
    for (int i = 0; i < HID; i++) {
      ho[i] = h[i];
      float s = e[i];
#pragma unroll
      for (int k = 0; k < HID; k++) s += A[i][k] * h[k];
      hn[i] = s;
    }
#pragma unroll
    for (int i = 0; i < HID; i++) h[i] = hn[i];
  }
}

// ============================================================================
// K4: transpose h chunk-major -> g_comb[:,10:20] (coalesced read, parallel)
// ============================================================================
__global__ void k4_transpose() {
  int idx = blockIdx.x * blockDim.x + threadIdx.x;   // over T_LEN*HID
  if (idx >= T_LEN * HID) return;
  int j = idx / (NCHUNK * HID);
  int r = idx % (NCHUNK * HID);
  int c = r / HID, i = r % HID;
  int t = c * CHL + j;
  g_comb[t * CDIM + EMB + i] = g_hcm[idx];
}

// ============================================================================
// K5: fused logits-GEMM + argmax. FFMA2, register weights, 2-t interleave,
//     FMNMX tournament (alu pipe) + REDUX warp argmax + single-lane atomicMax.
// ============================================================================
__global__ void __launch_bounds__(TPB, 2)
k5_argmax(const float* __restrict__ Wio, const float* __restrict__ bio) {
  __shared__ __align__(16) unsigned long long sc[TILE * CDIM];  // 40 KB
  int vslab = blockIdx.x % VSLABS;
  int tslab = blockIdx.x / VSLABS;
  int tid = threadIdx.x;
  int lane = tid & 31;
  int rbase = vslab * ROWS_PER_CTA + tid * (2 * PP);

  unsigned long long w2[PP][CDIM], b2[PP];
#pragma unroll
  for (int p = 0; p < PP; p++) {
    const float* r0 = &Wio[(rbase + 2 * p) * CDIM];
    const float* r1 = r0 + CDIM;
#pragma unroll
    for (int k = 0; k < CDIM; k++)
      w2[p][k] = pack2(__float_as_uint(r0[k]), __float_as_uint(r1[k]));
    b2[p] = pack2(__float_as_uint(bio[rbase + 2 * p]),
                  __float_as_uint(bio[rbase + 2 * p + 1]));
  }

  int t0 = tslab * TT;
  for (int tile = 0; tile < TT; tile += TILE) {
    __syncthreads();
    const float* src = &g_comb[(t0 + tile) * CDIM];
    for (int i = tid; i < TILE * CDIM; i += TPB) {
      unsigned int u = __float_as_uint(src[i]);
      sc[i] = pack2(u, u);
    }
    __syncthreads();

    for (int j = 0; j < TILE; j += 2) {
      const ulonglong2* cp0 = reinterpret_cast<const ulonglong2*>(&sc[j * CDIM]);
      const ulonglong2* cp1 = reinterpret_cast<const ulonglong2*>(&sc[(j + 1) * CDIM]);
      unsigned long long acc0[PP], acc1[PP];
#pragma unroll
      for (int p = 0; p < PP; p++) { acc0[p] = b2[p]; acc1[p] = b2[p]; }

#pragma unroll
      for (int q = 0; q < CDIM / 2; q++) {
        ulonglong2 a = cp0[q];
        ulonglong2 b = cp1[q];
#pragma unroll
        for (int p = 0; p < PP; p++) {
          acc0[p] = ffma2(w2[p][2 * q], a.x, acc0[p]);
          acc1[p] = ffma2(w2[p][2 * q], b.x, acc1[p]);
        }
#pragma unroll
        for (int p = 0; p < PP; p++) {
          acc0[p] = ffma2(w2[p][2 * q + 1], a.y, acc0[p]);
          acc1[p] = ffma2(w2[p][2 * q + 1], b.y, acc1[p]);
        }
      }

      // argmax for both t's: FMNMX tournament (alu pipe) + REDUX + ballot
#pragma unroll
      for (int s = 0; s < 2; s++) {
        unsigned long long* acc = s ? acc1 : acc0;
        float f[2 * PP];
#pragma unroll
        for (int p = 0; p < PP; p++) unpack2f(acc[p], f[2 * p], f[2 * p + 1]);
        float m01 = fmaxf(f[0], f[1]), m23 = fmaxf(f[2], f[3]);
        float m45 = fmaxf(f[4], f[5]), m67 = fmaxf(f[6], f[7]);
        float m03 = fmaxf(m01, m23), m47 = fmaxf(m45, m67);
        float lmax = fmaxf(m03, m47);
        unsigned int key = okey(lmax);
        unsigned int wm = __reduce_max_sync(0xffffffffu, key);
        unsigned int bal = __ballot_sync(0xffffffffu, key == wm);
        if (lane == __ffs(bal) - 1) {
          int off = (f[0] == lmax) ? 0
                  : (f[1] == lmax) ? 1
                  : (f[2] == lmax) ? 2
                  : (f[3] == lmax) ? 3
                  : (f[4] == lmax) ? 4
                  : (f[5] == lmax) ? 5
                  : (f[6] == lmax) ? 6 : 7;
          unsigned long long packed =
              ((unsigned long long)wm << 32) |
              (unsigned int)(~(unsigned int)(rbase + off));
          atomicMax(&g_best[t0 + tile + j + s], packed);
        }
      }
    }
  }
}

// ============================================================================
// K6: decode packed (key, ~idx) -> float index
// ============================================================================
__global__ void k6_out(float* __restrict__ out) {
  int t = blockIdx.x * blockDim.x + threadIdx.x;
  if (t < T_LEN) out[t] = (float)(~(unsigned int)g_best[t]);
}

extern "C" void kernel_launch(void* const* d_in, const int* in_sizes, int n_in,
                              void* d_out, int out_size) {
  const int*   ib  = (const int*)d_in[0];
  const float* emb = (const float*)d_in[1];
  const float* Wih = (const float*)d_in[2];
  const float* bih = (const float*)d_in[3];
  const float* Wio = (const float*)d_in[4];
  const float* bio = (const float*)d_in[5];
  float* out = (float*)d_out;

  k0_embed<<<T_LEN / 128, 128>>>(ib, emb, Wih, bih);
  k1_chunkv<<<NCHUNK / 128, 128>>>(Wih);
  k2_scan<<<1, 128>>>(Wih);
  k3_fill<<<NCHUNK / 128, 128>>>(Wih);
  k4_transpose<<<(T_LEN * HID + 127) / 128, 128>>>();
  k5_argmax<<<VSLABS * TSLABS, TPB>>>(Wio, bio);
  k6_out<<<T_LEN / 128, 128>>>(out);
}

// round 5
// speedup vs baseline: 2.1093x; 1.5045x over previous
#include <cuda_runtime.h>
#include <cuda_bf16.h>
#include <cstdint>

#define T_LEN 8192
#define VOCAB 128000
#define EMB 10
#define HID 10
#define CDIM 20
#define NCHUNK 1024
#define CHL 8
#define NGRP 32

// GEMM config (legacy mma.sync path)
#define KP 128                 // padded K (123 used)
#define NG 4                   // n-groups
#define MCTA 32                // m CTAs (8192/256)
#define CH_TOTAL 4000          // 128000/32
#define CH_PER_G (CH_TOTAL / NG)   // 1000
#define BROW_PAD 272           // 256B + 16B pad (ldmatrix conflict-free)

// ---- scratch globals ----
__device__ float g_comb[T_LEN * CDIM];
__device__ float g_ecm[T_LEN * HID];
__device__ float g_hcm[T_LEN * HID];
__device__ float g_v[NCHUNK * HID];
__device__ float g_hs[NCHUNK * HID];
__device__ unsigned long long g_best[T_LEN];
__device__ __align__(16) unsigned int g_aext[T_LEN * (KP / 2)];      // 2 MB, frag order
__device__ __align__(16) unsigned int g_bext[VOCAB * (KP / 2)];      // 32.8 MB, row-major

__device__ __forceinline__ unsigned int okey(float f) {
  unsigned int u = __float_as_uint(f);
  return u ^ ((unsigned int)((int)u >> 31) | 0x80000000u);
}
__device__ __forceinline__ uint32_t smem_u32(const void* p) {
  uint32_t a;
  asm("{ .reg .u64 t; cvta.to.shared.u64 t, %1; cvt.u32.u64 %0, t; }" : "=r"(a) : "l"(p));
  return a;
}
__device__ __forceinline__ unsigned short bfbits(float x) {
  __nv_bfloat16 b = __float2bfloat16(x);
  return *reinterpret_cast<unsigned short*>(&b);
}
// 3-way split of fp32 into bf16 (hi, mid, lo)
__device__ __forceinline__ void split3(float x, unsigned short& hi,
                                       unsigned short& mi, unsigned short& lo) {
  __nv_bfloat16 bh = __float2bfloat16(x);
  float fh = __bfloat162float(bh);
  __nv_bfloat16 bm = __float2bfloat16(x - fh);
  float fm = __bfloat162float(bm);
  __nv_bfloat16 bl = __float2bfloat16(x - fh - fm);
  hi = *reinterpret_cast<unsigned short*>(&bh);
  mi = *reinterpret_cast<unsigned short*>(&bm);
  lo = *reinterpret_cast<unsigned short*>(&bl);
}

// ============================================================================
// K0: embeddings -> combined[:,0:10]; e_t chunk-major; init g_best
// ============================================================================
__global__ void k0_embed(const int* __restrict__ ib, const float* __restrict__ emb,
                         const float* __restrict__ Wih, const float* __restrict__ bih) {
  int t = blockIdx.x * blockDim.x + threadIdx.x;
  if (t >= T_LEN) return;
  int ix = ib[t];
  float w[EMB];
#pragma unroll
  for (int k = 0; k < EMB; k++) {
    w[k] = emb[ix * EMB + k];
    g_comb[t * CDIM + k] = w[k];
  }
  int c = t / CHL, j = t % CHL;
  float* e = &g_ecm[(j * NCHUNK + c) * HID];
#pragma unroll
  for (int i = 0; i < HID; i++) {
    float s = bih[i];
#pragma unroll
    for (int k = 0; k < EMB; k++) s += Wih[i * CDIM + k] * w[k];
    e[i] = s;
  }
  g_best[t] = 0ULL;
}

// ============================================================================
// K1: per-chunk partial scan from h=0
// ============================================================================
__global__ void k1_chunkv(const float* __restrict__ Wih) {
  int c = blockIdx.x * blockDim.x + threadIdx.x;
  float A[HID][HID];
#pragma unroll
  for (int i = 0; i < HID; i++)
#pragma unroll
    for (int k = 0; k < HID; k++) A[i][k] = Wih[i * CDIM + EMB + k];
  float h[HID];
#pragma unroll
  for (int i = 0; i < HID; i++) h[i] = 0.f;
#pragma unroll
  for (int j = 0; j < CHL; j++) {
    const float* e = &g_ecm[(j * NCHUNK + c) * HID];
    float hn[HID];
#pragma unroll
    for (int i = 0; i < HID; i++) {
      float s = e[i];
#pragma unroll
      for (int k = 0; k < HID; k++) s += A[i][k] * h[k];
      hn[i] = s;
    }
#pragma unroll
    for (int i = 0; i < HID; i++) h[i] = hn[i];
  }
#pragma unroll
  for (int i = 0; i < HID; i++) g_v[c * HID + i] = h[i];
}

// ============================================================================
// K2: two-level chunk scan (M8=A^8, M256=M8^32) -> g_hs
// ============================================================================
__global__ void k2_scan(const float* __restrict__ Wih) {
  __shared__ float sM8[100], sM256[100], sT[100];
  __shared__ float sV[NCHUNK * 11];
  __shared__ float sgp[NGRP * 10], sge[NGRP * 10];
  int tid = threadIdx.x;

  if (tid < 100) sM8[tid] = Wih[(tid / 10) * CDIM + EMB + (tid % 10)];
  __syncthreads();
  for (int s = 0; s < 3; s++) {
    float acc = 0.f;
    if (tid < 100) {
      int i = tid / 10, k = tid % 10;
#pragma unroll
      for (int j = 0; j < 10; j++) acc += sM8[i * 10 + j] * sM8[j * 10 + k];
    }
    __syncthreads();
    if (tid < 100) sT[tid] = acc;
    __syncthreads();
    if (tid < 100) sM8[tid] = sT[tid];
    __syncthreads();
  }
  if (tid < 100) sM256[tid] = sM8[tid];
  __syncthreads();
  for (int s = 0; s < 5; s++) {
    float acc = 0.f;
    if (tid < 100) {
      int i = tid / 10, k = tid % 10;
#pragma unroll
      for (int j = 0; j < 10; j++) acc += sM256[i * 10 + j] * sM256[j * 10 + k];
    }
    __syncthreads();
    if (tid < 100) sT[tid] = acc;
    __syncthreads();
    if (tid < 100) sM256[tid] = sT[tid];
    __syncthreads();
  }
  for (int idx = tid; idx < NCHUNK * HID; idx += blockDim.x) {
    int ch = idx / HID, i = idx % HID;
    int g = ch / 32, c = ch % 32;
    sV[(c * 32 + g) * 11 + i] = g_v[idx];
  }
  __syncthreads();
  if (tid < NGRP) {
    float h[HID];
#pragma unroll
    for (int i = 0; i < HID; i++) h[i] = 0.f;
    for (int c = 0; c < 32; c++) {
      const float* v = &sV[(c * 32 + tid) * 11];
      float hn[HID];
#pragma unroll
      for (int i = 0; i < HID; i++) {
        float s = v[i];
#pragma unroll
        for (int k = 0; k < HID; k++) s += sM8[i * 10 + k] * h[k];
        hn[i] = s;
      }
#pragma unroll
      for (int i = 0; i < HID; i++) h[i] = hn[i];
    }
#pragma unroll
    for (int i = 0; i < HID; i++) sgp[tid * 10 + i] = h[i];
  }
  __syncthreads();
  if (tid == 0) {
    float h[HID];
#pragma unroll
    for (int i = 0; i < HID; i++) h[i] = 0.f;
    for (int g = 0; g < NGRP; g++) {
#pragma unroll
      for (int i = 0; i < HID; i++) sge[g * 10 + i] = h[i];
      float hn[HID];
#pragma unroll
      for (int i = 0; i < HID; i++) {
        float s = sgp[g * 10 + i];
#pragma unroll
        for (int k = 0; k < HID; k++) s += sM256[i * 10 + k] * h[k];
        hn[i] = s;
      }
#pragma unroll
      for (int i = 0; i < HID; i++) h[i] = hn[i];
    }
  }
  __syncthreads();
  if (tid < NGRP) {
    float h[HID];
#pragma unroll
    for (int i = 0; i < HID; i++) h[i] = sge[tid * 10 + i];
    for (int c = 0; c < 32; c++) {
      int ch = tid * 32 + c;
#pragma unroll
      for (int i = 0; i < HID; i++) g_hs[ch * HID + i] = h[i];
      const float* v = &sV[(c * 32 + tid) * 11];
      float hn[HID];
#pragma unroll
      for (int i = 0; i < HID; i++) {
        float s = v[i];
#pragma unroll
        for (int k = 0; k < HID; k++) s += sM8[i * 10 + k] * h[k];
        hn[i] = s;
      }
#pragma unroll
      for (int i = 0; i < HID; i++) h[i] = hn[i];
    }
  }
}

// ============================================================================
// K3: replay chunks -> h chunk-major
// ============================================================================
__global__ void k3_fill(const float* __restrict__ Wih) {
  int c = blockIdx.x * blockDim.x + threadIdx.x;
  float A[HID][HID];
#pragma unroll
  for (int i = 0; i < HID; i++)
#pragma unroll
    for (int k = 0; k < HID; k++) A[i][k] = Wih[i * CDIM + EMB + k];
  float h[HID];
#pragma unroll
  for (int i = 0; i < HID; i++) h[i] = g_hs[c * HID + i];
#pragma unroll
  for (int j = 0; j < CHL; j++) {
    const float* e = &g_ecm[(j * NCHUNK + c) * HID];
    float* ho = &g_hcm[(j * NCHUNK + c) * HID];
    float hn[HID];
#pragma unroll
    for (int i = 0; i < HID; i++) {
      ho[i] = h[i];
      float s = e[i];
#pragma unroll
      for (int k = 0; k < HID; k++) s += A[i][k] * h[k];
      hn[i] = s;
    }
#pragma unroll
    for (int i = 0; i < HID; i++) h[i] = hn[i];
  }
}

// ============================================================================
// K4: transpose h chunk-major -> g_comb[:,10:20]
// ============================================================================
__global__ void k4_transpose() {
  int idx = blockIdx.x * blockDim.x + threadIdx.x;
  if (idx >= T_LEN * HID) return;
  int j = idx / (NCHUNK * HID);
  int r = idx % (NCHUNK * HID);
  int c = r / HID, i = r % HID;
  int t = c * CHL + j;
  g_comb[t * CDIM + EMB + i] = g_hcm[idx];
}

// ============================================================================
// B prep: thread per vocab row. Row layout (u32 index j, k=2j):
//  [0,10) hi | [10,20) hi | [20,30) mid | [30,40) mid | [40,50) hi | [50,60) lo
//  j=60: (b_hi, b_mid)  j=61: (b_lo, 0)  j=62,63: 0
// ============================================================================
__global__ void k_bprep(const float* __restrict__ Wio, const float* __restrict__ bio) {
  int n = blockIdx.x * blockDim.x + threadIdx.x;
  if (n >= VOCAB) return;
  unsigned int uhi[10], umi[10], ulo[10];
#pragma unroll
  for (int p = 0; p < 10; p++) {
    unsigned short h0, m0, l0, h1, m1, l1;
    split3(Wio[n * CDIM + 2 * p], h0, m0, l0);
    split3(Wio[n * CDIM + 2 * p + 1], h1, m1, l1);
    uhi[p] = (unsigned int)h0 | ((unsigned int)h1 << 16);
    umi[p] = (unsigned int)m0 | ((unsigned int)m1 << 16);
    ulo[p] = (unsigned int)l0 | ((unsigned int)l1 << 16);
  }
  unsigned short bh, bm, bl;
  split3(bio[n], bh, bm, bl);
  unsigned int* out = &g_bext[n * 64];
#pragma unroll
  for (int p = 0; p < 10; p++) {
    out[p] = uhi[p];
    out[10 + p] = uhi[p];
    out[20 + p] = umi[p];
    out[30 + p] = umi[p];
    out[40 + p] = uhi[p];
    out[50 + p] = ulo[p];
  }
  out[60] = (unsigned int)bh | ((unsigned int)bm << 16);
  out[61] = (unsigned int)bl;
  out[62] = 0;
  out[63] = 0;
}

// ============================================================================
// A prep: thread per t. A segs: hi mid hi mid lo hi; k=120..122 -> 1.0f.
// Fragment-order layout: u32 idx = sw*2048 + mf*1024 + ks*128 + l*4 + r
// ============================================================================
__global__ void k_aprep() {
  int t = blockIdx.x * blockDim.x + threadIdx.x;
  if (t >= T_LEN) return;
  unsigned short hi[CDIM], mi[CDIM], lo[CDIM];
#pragma unroll
  for (int i = 0; i < CDIM; i++) split3(g_comb[t * CDIM + i], hi[i], mi[i], lo[i]);
  const unsigned short one = 0x3F80;  // bf16(1.0)
  int sw = t >> 5;
  int mf = (t >> 4) & 1;
  int l4 = t & 7;          // l/4
  int rlo = (t >> 3) & 1;  // r bit0
  unsigned int base = sw * 2048 + mf * 1024;
#pragma unroll
  for (int j = 0; j < 64; j++) {
    int k = 2 * j;
    unsigned short v0 = 0, v1 = 0;
    if (k < 120) {
      int seg = k / 20, wi = k % 20;
      if (seg == 0 || seg == 2 || seg == 5) { v0 = hi[wi]; v1 = hi[wi + 1]; }
      else if (seg == 1 || seg == 3)        { v0 = mi[wi]; v1 = mi[wi + 1]; }
      else                                  { v0 = lo[wi]; v1 = lo[wi + 1]; }
    } else if (k == 120) { v0 = one; v1 = one; }
    else if (k == 122)   { v0 = one; v1 = 0; }
    unsigned int u = (unsigned int)v0 | ((unsigned int)v1 << 16);
    int ks = j >> 3;
    int l = l4 * 4 + (j & 3);
    int r = ((j >> 2) & 1) * 2 + rlo;
    g_aext[base + ks * 128 + l * 4 + r] = u;
  }
}

// ============================================================================
// K5: bf16 mma.sync GEMM + per-row running (max, chunk) epilogue.
//   CTA: 256 thr = 8 warps, m256 slab; grid = 32 mCTAs x 4 ngroups.
//   A frags in registers; B double-buffered smem (272B rows, ldmatrix).
// ============================================================================
__global__ void __launch_bounds__(256, 1) k5_mma() {
  __shared__ __align__(16) char sB[2][32 * BROW_PAD];
  int tid = threadIdx.x, w = tid >> 5, lane = tid & 31;
  int ctam = blockIdx.x >> 2, ngrp = blockIdx.x & 3;
  int sw = ctam * 8 + w;

  // A fragments: 16 x uint4 per thread
  uint4 afr[8][2];
  {
    const uint4* ab = reinterpret_cast<const uint4*>(&g_aext[sw * 2048]);
#pragma unroll
    for (int mf = 0; mf < 2; mf++)
#pragma unroll
      for (int ks = 0; ks < 8; ks++) afr[ks][mf] = ab[(mf * 8 + ks) * 32 + lane];
  }

  float rv[4];
  int rc[4];
#pragma unroll
  for (int i = 0; i < 4; i++) { rv[i] = -3.4e38f; rc[i] = 0; }

  const uint4* bg0 = reinterpret_cast<const uint4*>(&g_bext[(size_t)(ngrp * CH_PER_G) * 32 * 64]);
  // prefetch chunk 0 and stage
  uint4 pf0 = bg0[tid], pf1 = bg0[tid + 256];
  {
    int u0 = tid, u1 = tid + 256;
    *reinterpret_cast<uint4*>(&sB[0][(u0 >> 4) * BROW_PAD + (u0 & 15) * 16]) = pf0;
    *reinterpret_cast<uint4*>(&sB[0][(u1 >> 4) * BROW_PAD + (u1 & 15) * 16]) = pf1;
  }
  __syncthreads();

  for (int s = 0; s < CH_PER_G; s++) {
    if (s + 1 < CH_PER_G) {
      const uint4* bg = bg0 + (size_t)(s + 1) * 512;
      pf0 = bg[tid];
      pf1 = bg[tid + 256];
    }
    // ---- compute chunk s ----
    float C[2][4][4];
#pragma unroll
    for (int mf = 0; mf < 2; mf++)
#pragma unroll
      for (int nf = 0; nf < 4; nf++)
#pragma unroll
        for (int i = 0; i < 4; i++) C[mf][nf][i] = 0.f;

    uint32_t sb0 = smem_u32(&sB[s & 1][0]);
    int grp = lane >> 3, lr = lane & 7;
#pragma unroll
    for (int ks = 0; ks < 8; ks++) {
      unsigned int bb[4][2];
#pragma unroll
      for (int p = 0; p < 2; p++) {
        uint32_t addr = sb0 + (p * 16 + (grp & 1) * 8 + lr) * BROW_PAD +
                        ((grp >> 1) << 4) + ks * 32;
        unsigned int r0, r1, r2, r3;
        asm volatile(
            "ldmatrix.sync.aligned.m8n8.x4.shared.b16 {%0,%1,%2,%3}, [%4];"
            : "=r"(r0), "=r"(r1), "=r"(r2), "=r"(r3) : "r"(addr));
        bb[2 * p][0] = r0; bb[2 * p + 1][0] = r1;
        bb[2 * p][1] = r2; bb[2 * p + 1][1] = r3;
      }
#pragma unroll
      for (int nf = 0; nf < 4; nf++)
#pragma unroll
        for (int mf = 0; mf < 2; mf++) {
          asm volatile(
              "mma.sync.aligned.m16n8k16.row.col.f32.bf16.bf16.f32 "
              "{%0,%1,%2,%3}, {%4,%5,%6,%7}, {%8,%9}, {%0,%1,%2,%3};"
              : "+f"(C[mf][nf][0]), "+f"(C[mf][nf][1]),
                "+f"(C[mf][nf][2]), "+f"(C[mf][nf][3])
              : "r"(afr[ks][mf].x), "r"(afr[ks][mf].y),
                "r"(afr[ks][mf].z), "r"(afr[ks][mf].w),
                "r"(bb[nf][0]), "r"(bb[nf][1]));
        }
    }
    // ---- epilogue: per-row max over this chunk's 8 thread-local cols ----
    int gch = ngrp * CH_PER_G + s;
#pragma unroll
    for (int i = 0; i < 4; i++) {
      int mf = i >> 1, hb = i & 1;
      float m0 = fmaxf(C[mf][0][hb * 2], C[mf][0][hb * 2 + 1]);
      float m1 = fmaxf(C[mf][1][hb * 2], C[mf][1][hb * 2 + 1]);
      float m2 = fmaxf(C[mf][2][hb * 2], C[mf][2][hb * 2 + 1]);
      float m3 = fmaxf(C[mf][3][hb * 2], C[mf][3][hb * 2 + 1]);
      float m8 = fmaxf(fmaxf(m0, m1), fmaxf(m2, m3));
      if (m8 > rv[i]) { rv[i] = m8; rc[i] = gch; }
    }
    // ---- stage chunk s+1 ----
    if (s + 1 < CH_PER_G) {
      char* nb = sB[(s + 1) & 1];
      int u0 = tid, u1 = tid + 256;
      *reinterpret_cast<uint4*>(&nb[(u0 >> 4) * BROW_PAD + (u0 & 15) * 16]) = pf0;
      *reinterpret_cast<uint4*>(&nb[(u1 >> 4) * BROW_PAD + (u1 & 15) * 16]) = pf1;
    }
    __syncthreads();
  }

  // final: quad-reduce (value, chunk) and atomicMax per row
#pragma unroll
  for (int i = 0; i < 4; i++) {
    unsigned long long pk = ((unsigned long long)okey(rv[i]) << 32) |
                            (unsigned int)(~(unsigned int)rc[i]);
    unsigned long long o1 = __shfl_xor_sync(0xffffffffu, pk, 1);
    if (o1 > pk) pk = o1;
    unsigned long long o2 = __shfl_xor_sync(0xffffffffu, pk, 2);
    if (o2 > pk) pk = o2;
    if ((lane & 3) == 0) {
      int t = ctam * 256 + w * 32 + i * 8 + (lane >> 2);
      atomicMax(&g_best[t], pk);
    }
  }
}

// ============================================================================
// K7: rescue — exact fp32 argmax inside winning 32-row chunk; write output.
// ============================================================================
__global__ void k7_rescue(const float* __restrict__ Wio, const float* __restrict__ bio,
                          float* __restrict__ out) {
  int warp = (blockIdx.x * blockDim.x + threadIdx.x) >> 5;
  int lane = threadIdx.x & 31;
  if (warp >= T_LEN) return;
  int t = warp;
  unsigned int chunk = ~(unsigned int)g_best[t];
  int n = chunk * 32 + lane;
  float s = bio[n];
  const float* wr = &Wio[n * CDIM];
  const float* c = &g_comb[t * CDIM];
#pragma unroll
  for (int k = 0; k < CDIM; k++) s += wr[k] * c[k];
  unsigned int key = okey(s);
  unsigned int m = __reduce_max_sync(0xffffffffu, key);
  unsigned int bal = __ballot_sync(0xffffffffu, key == m);
  if (lane == 0) out[t] = (float)(chunk * 32 + (__ffs(bal) - 1));
}

extern "C" void kernel_launch(void* const* d_in, const int* in_sizes, int n_in,
                              void* d_out, int out_size) {
  const int*   ib  = (const int*)d_in[0];
  const float* emb = (const float*)d_in[1];
  const float* Wih = (const float*)d_in[2];
  const float* bih = (const float*)d_in[3];
  const float* Wio = (const float*)d_in[4];
  const float* bio = (const float*)d_in[5];
  float* out = (float*)d_out;

  k_bprep<<<VOCAB / 128, 128>>>(Wio, bio);
  k0_embed<<<T_LEN / 128, 128>>>(ib, emb, Wih, bih);
  k1_chunkv<<<NCHUNK / 128, 128>>>(Wih);
  k2_scan<<<1, 128>>>(Wih);
  k3_fill<<<NCHUNK / 128, 128>>>(Wih);
  k4_transpose<<<(T_LEN * HID + 127) / 128, 128>>>();
  k_aprep<<<T_LEN / 128, 128>>>();
  k5_mma<<<MCTA * NG, 256>>>();
  k7_rescue<<<T_LEN / 8, 256>>>(Wio, bio, out);
}

// round 6
// speedup vs baseline: 2.7013x; 1.2806x over previous
#include <cuda_runtime.h>
#include <cuda_fp16.h>
#include <cstdint>

#define T_LEN 8192
#define VOCAB 128000
#define EMB 10
#define HID 10
#define CDIM 20
#define NCHUNK 1024
#define CHL 8
#define NGRP 32

// GEMM config (legacy mma.sync path, fp16 2-way split, K=64)
#define KP 64
#define NG 4                   // n-groups
#define MCTA 32                // m CTAs (8192/256)
#define CH_TOTAL 4000          // 128000/32
#define CH_PER_G (CH_TOTAL / NG)   // 1000
#define BROW_PAD 144           // 128B row + 16B pad (ldmatrix conflict-free)

// ---- scratch globals ----
__device__ float g_comb[T_LEN * CDIM];
__device__ float g_ecm[T_LEN * HID];
__device__ float g_hcm[T_LEN * HID];
__device__ float g_v[NCHUNK * HID];
__device__ float g_hs[NCHUNK * HID];
__device__ unsigned long long g_cand[T_LEN * 8];   // [t][ngrp][2] packed (okey, chunk)
__device__ __align__(16) unsigned int g_aext[T_LEN * (KP / 2)];   // 1 MB, frag order
__device__ __align__(16) unsigned int g_bext[VOCAB * (KP / 2)];   // 16.4 MB row-major

__device__ __forceinline__ unsigned int okey(float f) {
  unsigned int u = __float_as_uint(f);
  return u ^ ((unsigned int)((int)u >> 31) | 0x80000000u);
}
__device__ __forceinline__ uint32_t smem_u32(const void* p) {
  uint32_t a;
  asm("{ .reg .u64 t; cvta.to.shared.u64 t, %1; cvt.u32.u64 %0, t; }" : "=r"(a) : "l"(p));
  return a;
}
// 2-way split of fp32 into fp16 (hi, lo)
__device__ __forceinline__ void split2(float x, unsigned short& hi, unsigned short& lo) {
  __half h = __float2half_rn(x);
  float fh = __half2float(h);
  __half l = __float2half_rn(x - fh);
  hi = *reinterpret_cast<unsigned short*>(&h);
  lo = *reinterpret_cast<unsigned short*>(&l);
}
// merge top-2 distinct-chunk candidates (packed u64: value-key hi, chunk lo)
__device__ __forceinline__ void merge2(unsigned long long& a1, unsigned long long& a2,
                                       unsigned long long b1, unsigned long long b2) {
  if (a1 >= b1) {
    unsigned long long cand = ((unsigned int)b1 == (unsigned int)a1) ? b2 : b1;
    if (cand > a2) a2 = cand;
  } else {
    unsigned long long n2 = ((unsigned int)a1 == (unsigned int)b1) ? a2 : a1;
    a2 = (n2 >= b2) ? n2 : b2;
    a1 = b1;
  }
}

// ============================================================================
// K0: embeddings -> combined[:,0:10]; e_t chunk-major
// ============================================================================
__global__ void k0_embed(const int* __restrict__ ib, const float* __restrict__ emb,
                         const float* __restrict__ Wih, const float* __restrict__ bih) {
  int t = blockIdx.x * blockDim.x + threadIdx.x;
  if (t >= T_LEN) return;
  int ix = ib[t];
  float w[EMB];
#pragma unroll
  for (int k = 0; k < EMB; k++) {
    w[k] = emb[ix * EMB + k];
    g_comb[t * CDIM + k] = w[k];
  }
  int c = t / CHL, j = t % CHL;
  float* e = &g_ecm[(j * NCHUNK + c) * HID];
#pragma unroll
  for (int i = 0; i < HID; i++) {
    float s = bih[i];
#pragma unroll
    for (int k = 0; k < EMB; k++) s += Wih[i * CDIM + k] * w[k];
    e[i] = s;
  }
}

// ============================================================================
// K1: per-chunk partial scan from h=0
// ============================================================================
__global__ void k1_chunkv(const float* __restrict__ Wih) {
  int c = blockIdx.x * blockDim.x + threadIdx.x;
  float A[HID][HID];
#pragma unroll
  for (int i = 0; i < HID; i++)
#pragma unroll
    for (int k = 0; k < HID; k++) A[i][k] = Wih[i * CDIM + EMB + k];
  float h[HID];
#pragma unroll
  for (int i = 0; i < HID; i++) h[i] = 0.f;
#pragma unroll
  for (int j = 0; j < CHL; j++) {
    const float* e = &g_ecm[(j * NCHUNK + c) * HID];
    float hn[HID];
#pragma unroll
    for (int i = 0; i < HID; i++) {
      float s = e[i];
#pragma unroll
      for (int k = 0; k < HID; k++) s += A[i][k] * h[k];
      hn[i] = s;
    }
#pragma unroll
    for (int i = 0; i < HID; i++) h[i] = hn[i];
  }
#pragma unroll
  for (int i = 0; i < HID; i++) g_v[c * HID + i] = h[i];
}

// ============================================================================
// K2: two-level chunk scan (M8=A^8, M256=M8^32) -> g_hs
// ============================================================================
__global__ void k2_scan(const float* __restrict__ Wih) {
  __shared__ float sM8[100], sM256[100], sT[100];
  __shared__ float sV[NCHUNK * 11];
  __shared__ float sgp[NGRP * 10], sge[NGRP * 10];
  int tid = threadIdx.x;

  if (tid < 100) sM8[tid] = Wih[(tid / 10) * CDIM + EMB + (tid % 10)];
  __syncthreads();
  for (int s = 0; s < 3; s++) {
    float acc = 0.f;
    if (tid < 100) {
      int i = tid / 10, k = tid % 10;
#pragma unroll
      for (int j = 0; j < 10; j++) acc += sM8[i * 10 + j] * sM8[j * 10 + k];
    }
    __syncthreads();
    if (tid < 100) sT[tid] = acc;
    __syncthreads();
    if (tid < 100) sM8[tid] = sT[tid];
    __syncthreads();
  }
  if (tid < 100) sM256[tid] = sM8[tid];
  __syncthreads();
  for (int s = 0; s < 5; s++) {
    float acc = 0.f;
    if (tid < 100) {
      int i = tid / 10, k = tid % 10;
#pragma unroll
      for (int j = 0; j < 10; j++) acc += sM256[i * 10 + j] * sM256[j * 10 + k];
    }
    __syncthreads();
    if (tid < 100) sT[tid] = acc;
    __syncthreads();
    if (tid < 100) sM256[tid] = sT[tid];
    __syncthreads();
  }
  for (int idx = tid; idx < NCHUNK * HID; idx += blockDim.x) {
    int ch = idx / HID, i = idx % HID;
    int g = ch / 32, c = ch % 32;
    sV[(c * 32 + g) * 11 + i] = g_v[idx];
  }
  __syncthreads();
  if (tid < NGRP) {
    float h[HID];
#pragma unroll
    for (int i = 0; i < HID; i++) h[i] = 0.f;
    for (int c = 0; c < 32; c++) {
      const float* v = &sV[(c * 32 + tid) * 11];
      float hn[HID];
#pragma unroll
      for (int i = 0; i < HID; i++) {
        float s = v[i];
#pragma unroll
        for (int k = 0; k < HID; k++) s += sM8[i * 10 + k] * h[k];
        hn[i] = s;
      }
#pragma unroll
      for (int i = 0; i < HID; i++) h[i] = hn[i];
    }
#pragma unroll
    for (int i = 0; i < HID; i++) sgp[tid * 10 + i] = h[i];
  }
  __syncthreads();
  if (tid == 0) {
    float h[HID];
#pragma unroll
    for (int i = 0; i < HID; i++) h[i] = 0.f;
    for (int g = 0; g < NGRP; g++) {
#pragma unroll
      for (int i = 0; i < HID; i++) sge[g * 10 + i] = h[i];
      float hn[HID];
#pragma unroll
      for (int i = 0; i < HID; i++) {
        float s = sgp[g * 10 + i];
#pragma unroll
        for (int k = 0; k < HID; k++) s += sM256[i * 10 + k] * h[k];
        hn[i] = s;
      }
#pragma unroll
      for (int i = 0; i < HID; i++) h[i] = hn[i];
    }
  }
  __syncthreads();
  if (tid < NGRP) {
    float h[HID];
#pragma unroll
    for (int i = 0; i < HID; i++) h[i] = sge[tid * 10 + i];
    for (int c = 0; c < 32; c++) {
      int ch = tid * 32 + c;
#pragma unroll
      for (int i = 0; i < HID; i++) g_hs[ch * HID + i] = h[i];
      const float* v = &sV[(c * 32 + tid) * 11];
      float hn[HID];
#pragma unroll
      for (int i = 0; i < HID; i++) {
        float s = v[i];
#pragma unroll
        for (int k = 0; k < HID; k++) s += sM8[i * 10 + k] * h[k];
        hn[i] = s;
      }
#pragma unroll
      for (int i = 0; i < HID; i++) h[i] = hn[i];
    }
  }
}

// ============================================================================
// K3: replay chunks -> h chunk-major
// ============================================================================
__global__ void k3_fill(const float* __restrict__ Wih) {
  int c = blockIdx.x * blockDim.x + threadIdx.x;
  float A[HID][HID];
#pragma unroll
  for (int i = 0; i < HID; i++)
#pragma unroll
    for (int k = 0; k < HID; k++) A[i][k] = Wih[i * CDIM + EMB + k];
  float h[HID];
#pragma unroll
  for (int i = 0; i < HID; i++) h[i] = g_hs[c * HID + i];
#pragma unroll
  for (int j = 0; j < CHL; j++) {
    const float* e = &g_ecm[(j * NCHUNK + c) * HID];
    float* ho = &g_hcm[(j * NCHUNK + c) * HID];
    float hn[HID];
#pragma unroll
    for (int i = 0; i < HID; i++) {
      ho[i] = h[i];
      float s = e[i];
#pragma unroll
      for (int k = 0; k < HID; k++) s += A[i][k] * h[k];
      hn[i] = s;
    }
#pragma unroll
    for (int i = 0; i < HID; i++) h[i] = hn[i];
  }
}

// ============================================================================
// K4: transpose h chunk-major -> g_comb[:,10:20]
// ============================================================================
__global__ void k4_transpose() {
  int idx = blockIdx.x * blockDim.x + threadIdx.x;
  if (idx >= T_LEN * HID) return;
  int j = idx / (NCHUNK * HID);
  int r = idx % (NCHUNK * HID);
  int c = r / HID, i = r % HID;
  int t = c * CHL + j;
  g_comb[t * CDIM + EMB + i] = g_hcm[idx];
}

// ============================================================================
// B prep: row layout (u32 j, k=2j):
//   j[0,10): hi  | j[10,20): hi | j[20,30): lo | j=30: (b_hi, b_lo) | j=31: 0
// (products: A hi.B hi, A lo.B hi, A hi.B lo, bias)
// ============================================================================
__global__ void k_bprep(const float* __restrict__ Wio, const float* __restrict__ bio) {
  int n = blockIdx.x * blockDim.x + threadIdx.x;
  if (n >= VOCAB) return;
  unsigned int uhi[10], ulo[10];
#pragma unroll
  for (int p = 0; p < 10; p++) {
    unsigned short h0, l0, h1, l1;
    split2(Wio[n * CDIM + 2 * p], h0, l0);
    split2(Wio[n * CDIM + 2 * p + 1], h1, l1);
    uhi[p] = (unsigned int)h0 | ((unsigned int)h1 << 16);
    ulo[p] = (unsigned int)l0 | ((unsigned int)l1 << 16);
  }
  unsigned short bh, bl;
  split2(bio[n], bh, bl);
  unsigned int* out = &g_bext[n * 32];
#pragma unroll
  for (int p = 0; p < 10; p++) {
    out[p] = uhi[p];
    out[10 + p] = uhi[p];
    out[20 + p] = ulo[p];
  }
  out[30] = (unsigned int)bh | ((unsigned int)bl << 16);
  out[31] = 0;
}

// ============================================================================
// A prep: j[0,10): hi | j[10,20): lo | j[20,30): hi | j=30: (1,1) | j=31: 0
// Fragment order: u32 idx = (t>>5)*1024 + mf*512 + ks*128 + lane*4 + r
// ============================================================================
__global__ void k_aprep() {
  int t = blockIdx.x * blockDim.x + threadIdx.x;
  if (t >= T_LEN) return;
  unsigned short hi[CDIM], lo[CDIM];
#pragma unroll
  for (int i = 0; i < CDIM; i++) split2(g_comb[t * CDIM + i], hi[i], lo[i]);
  const unsigned short one = 0x3C00;  // fp16(1.0)
  unsigned int base = (t >> 5) * 1024 + ((t >> 4) & 1) * 512;
  int rowlo = (t >> 3) & 1;
  int lhi = (t & 7) * 4;
#pragma unroll
  for (int j = 0; j < 32; j++) {
    unsigned short v0 = 0, v1 = 0;
    if (j < 10)       { v0 = hi[2 * j];        v1 = hi[2 * j + 1]; }
    else if (j < 20)  { v0 = lo[2 * (j - 10)]; v1 = lo[2 * (j - 10) + 1]; }
    else if (j < 30)  { v0 = hi[2 * (j - 20)]; v1 = hi[2 * (j - 20) + 1]; }
    else if (j == 30) { v0 = one; v1 = one; }
    unsigned int u = (unsigned int)v0 | ((unsigned int)v1 << 16);
    int ks = j >> 3;
    int lane = lhi + (j & 3);
    int r = ((j >> 2) & 1) * 2 + rowlo;
    g_aext[base + ks * 128 + lane * 4 + r] = u;
  }
}

// ============================================================================
// K5: fp16 mma.sync GEMM (K=64) + per-row top-2-chunk epilogue.
//   CTA: 256 thr = 8 warps, 256-row m slab; grid = 32 mCTAs x 4 ngroups.
// ============================================================================
__global__ void __launch_bounds__(256, 1) k5_mma() {
  __shared__ __align__(16) char sB[2][32 * BROW_PAD];
  int tid = threadIdx.x, w = tid >> 5, lane = tid & 31;
  int ctam = blockIdx.x >> 2, ngrp = blockIdx.x & 3;
  int sw = ctam * 8 + w;

  // A fragments: 8 x uint4 per thread
  uint4 afr[4][2];
  {
    const uint4* ab = reinterpret_cast<const uint4*>(&g_aext[sw * 1024]);
#pragma unroll
    for (int mf = 0; mf < 2; mf++)
#pragma unroll
      for (int ks = 0; ks < 4; ks++) afr[ks][mf] = ab[(mf * 4 + ks) * 32 + lane];
  }

  float rv1[4], rv2[4];
  int rc1[4], rc2[4];
#pragma unroll
  for (int i = 0; i < 4; i++) { rv1[i] = -3.4e38f; rv2[i] = -3.4e38f; rc1[i] = 0; rc2[i] = 0; }

  const uint4* bg0 = reinterpret_cast<const uint4*>(&g_bext[(size_t)(ngrp * CH_PER_G) * 32 * 32]);
  uint4 pf = bg0[tid];
  *reinterpret_cast<uint4*>(&sB[0][(tid >> 3) * BROW_PAD + (tid & 7) * 16]) = pf;
  __syncthreads();

  for (int s = 0; s < CH_PER_G; s++) {
    if (s + 1 < CH_PER_G) pf = bg0[(size_t)(s + 1) * 256 + tid];

    float C[2][4][4];
#pragma unroll
    for (int mf = 0; mf < 2; mf++)
#pragma unroll
      for (int nf = 0; nf < 4; nf++)
#pragma unroll
        for (int i = 0; i < 4; i++) C[mf][nf][i] = 0.f;

    uint32_t sb0 = smem_u32(&sB[s & 1][0]);
    int grp = lane >> 3, lr = lane & 7;
#pragma unroll
    for (int ks = 0; ks < 4; ks++) {
      unsigned int bb[4][2];
#pragma unroll
      for (int p = 0; p < 2; p++) {
        uint32_t addr = sb0 + (p * 16 + (grp & 1) * 8 + lr) * BROW_PAD +
                        ((grp >> 1) << 4) + ks * 32;
        unsigned int r0, r1, r2, r3;
        asm volatile(
            "ldmatrix.sync.aligned.m8n8.x4.shared.b16 {%0,%1,%2,%3}, [%4];"
            : "=r"(r0), "=r"(r1), "=r"(r2), "=r"(r3) : "r"(addr));
        bb[2 * p][0] = r0; bb[2 * p + 1][0] = r1;
        bb[2 * p][1] = r2; bb[2 * p + 1][1] = r3;
      }
#pragma unroll
      for (int nf = 0; nf < 4; nf++)
#pragma unroll
        for (int mf = 0; mf < 2; mf++) {
          asm volatile(
              "mma.sync.aligned.m16n8k16.row.col.f32.f16.f16.f32 "
              "{%0,%1,%2,%3}, {%4,%5,%6,%7}, {%8,%9}, {%0,%1,%2,%3};"
              : "+f"(C[mf][nf][0]), "+f"(C[mf][nf][1]),
                "+f"(C[mf][nf][2]), "+f"(C[mf][nf][3])
              : "r"(afr[ks][mf].x), "r"(afr[ks][mf].y),
                "r"(afr[ks][mf].z), "r"(afr[ks][mf].w),
                "r"(bb[nf][0]), "r"(bb[nf][1]));
        }
    }
    // epilogue: per-row chunk max, maintain top-2 distinct chunks
    int gch = ngrp * CH_PER_G + s;
#pragma unroll
    for (int i = 0; i < 4; i++) {
      int mf = i >> 1, hb = i & 1;
      float m0 = fmaxf(C[mf][0][hb * 2], C[mf][0][hb * 2 + 1]);
      float m1 = fmaxf(C[mf][1][hb * 2], C[mf][1][hb * 2 + 1]);
      float m2 = fmaxf(C[mf][2][hb * 2], C[mf][2][hb * 2 + 1]);
      float m3 = fmaxf(C[mf][3][hb * 2], C[mf][3][hb * 2 + 1]);
      float m8 = fmaxf(fmaxf(m0, m1), fmaxf(m2, m3));
      if (m8 > rv1[i]) {
        rv2[i] = rv1[i]; rc2[i] = rc1[i];
        rv1[i] = m8; rc1[i] = gch;
      } else if (m8 > rv2[i]) {
        rv2[i] = m8; rc2[i] = gch;
      }
    }
    // stage chunk s+1
    if (s + 1 < CH_PER_G) {
      *reinterpret_cast<uint4*>(&sB[(s + 1) & 1][(tid >> 3) * BROW_PAD + (tid & 7) * 16]) = pf;
    }
    __syncthreads();
  }

  // quad merge of top-2 candidates; plain stores (no atomics)
#pragma unroll
  for (int i = 0; i < 4; i++) {
    unsigned long long p1 = ((unsigned long long)okey(rv1[i]) << 32) | (unsigned int)rc1[i];
    unsigned long long p2 = ((unsigned long long)okey(rv2[i]) << 32) | (unsigned int)rc2[i];
#pragma unroll
    for (int off = 1; off <= 2; off <<= 1) {
      unsigned long long o1 = __shfl_xor_sync(0xffffffffu, p1, off);
      unsigned long long o2 = __shfl_xor_sync(0xffffffffu, p2, off);
      merge2(p1, p2, o1, o2);
    }
    if ((lane & 3) == 0) {
      int t = ctam * 256 + w * 32 + i * 8 + (lane >> 2);
      g_cand[t * 8 + ngrp * 2 + 0] = p1;
      g_cand[t * 8 + ngrp * 2 + 1] = p2;
    }
  }
}

// ============================================================================
// K7: rescue — exact fp32 argmax over 8 candidate chunks (256 rows) per t.
// ============================================================================
__global__ void k7_rescue(const float* __restrict__ Wio, const float* __restrict__ bio,
                          float* __restrict__ out) {
  int warp = (blockIdx.x * blockDim.x + threadIdx.x) >> 5;
  int lane = threadIdx.x & 31;
  if (warp >= T_LEN) return;
  int t = warp;
  float c[CDIM];
#pragma unroll
  for (int k = 0; k < CDIM; k++) c[k] = g_comb[t * CDIM + k];
  unsigned long long best = 0ULL;
#pragma unroll
  for (int ci = 0; ci < 8; ci++) {
    unsigned int chunk = (unsigned int)g_cand[t * 8 + ci];
    int n = chunk * 32 + lane;
    float s = bio[n];
    const float* wr = &Wio[n * CDIM];
#pragma unroll
    for (int k = 0; k < CDIM; k++) s += wr[k] * c[k];
    unsigned long long pk = ((unsigned long long)okey(s) << 32) |
                            (unsigned int)(~(unsigned int)n);
    if (pk > best) best = pk;
  }
#pragma unroll
  for (int off = 16; off; off >>= 1) {
    unsigned long long o = __shfl_down_sync(0xffffffffu, best, off);
    if (o > best) best = o;
  }
  if (lane == 0) out[t] = (float)(~(unsigned int)best);
}

extern "C" void kernel_launch(void* const* d_in, const int* in_sizes, int n_in,
                              void* d_out, int out_size) {
  const int*   ib  = (const int*)d_in[0];
  const float* emb = (const float*)d_in[1];
  const float* Wih = (const float*)d_in[2];
  const float* bih = (const float*)d_in[3];
  const float* Wio = (const float*)d_in[4];
  const float* bio = (const float*)d_in[5];
  float* out = (float*)d_out;

  k_bprep<<<VOCAB / 128, 128>>>(Wio, bio);
  k0_embed<<<T_LEN / 128, 128>>>(ib, emb, Wih, bih);
  k1_chunkv<<<NCHUNK / 128, 128>>>(Wih);
  k2_scan<<<1, 128>>>(Wih);
  k3_fill<<<NCHUNK / 128, 128>>>(Wih);
  k4_transpose<<<(T_LEN * HID + 127) / 128, 128>>>();
  k_aprep<<<T_LEN / 128, 128>>>();
  k5_mma<<<MCTA * NG, 256>>>();
  k7_rescue<<<T_LEN / 8, 256>>>(Wio, bio, out);
}

// round 7
// speedup vs baseline: 3.0732x; 1.1377x over previous
#include <cuda_runtime.h>
#include <cuda_fp16.h>
#include <cstdint>

#define T_LEN 8192
#define VOCAB 128000
#define EMB 10
#define HID 10
#define CDIM 20
#define NCHUNK 1024
#define CHL 8
#define NGRP 32

// GEMM config (legacy mma.sync, fp16 2-way split, K=64)
#define KP 64
#define NG 8                   // n-groups
#define MCTA 32                // m CTAs (8192/256)
#define CH_TOTAL 4000          // 128000/32
#define CH_PER_G (CH_TOTAL / NG)   // 500
#define STAGES (CH_PER_G / 2)      // 250 (2 chunks per stage)
#define BROW_PAD 144           // 128B row + 16B pad (ldmatrix conflict-free)

// ---- scratch globals ----
__device__ float g_comb[T_LEN * CDIM];
__device__ float g_ecm[T_LEN * HID];
__device__ float g_hcm[T_LEN * HID];
__device__ float g_v[NCHUNK * HID];
__device__ float g_hs[NCHUNK * HID];
__device__ unsigned long long g_cand[T_LEN * 16];  // [t][ngrp][2] packed (okey, chunk)
__device__ __align__(16) unsigned int g_aext[T_LEN * (KP / 2)];   // 1 MB frag order
__device__ __align__(16) unsigned int g_bext[VOCAB * (KP / 2)];   // 16.4 MB row-major

__device__ __forceinline__ unsigned int okey(float f) {
  unsigned int u = __float_as_uint(f);
  return u ^ ((unsigned int)((int)u >> 31) | 0x80000000u);
}
__device__ __forceinline__ uint32_t smem_u32(const void* p) {
  uint32_t a;
  asm("{ .reg .u64 t; cvta.to.shared.u64 t, %1; cvt.u32.u64 %0, t; }" : "=r"(a) : "l"(p));
  return a;
}
// 2-way split of fp32 into fp16 (hi, lo)
__device__ __forceinline__ void split2(float x, unsigned short& hi, unsigned short& lo) {
  __half h = __float2half_rn(x);
  float fh = __half2float(h);
  __half l = __float2half_rn(x - fh);
  hi = *reinterpret_cast<unsigned short*>(&h);
  lo = *reinterpret_cast<unsigned short*>(&l);
}
// merge top-2 distinct-chunk candidates (packed u64: value-key hi, chunk lo)
__device__ __forceinline__ void merge2(unsigned long long& a1, unsigned long long& a2,
                                       unsigned long long b1, unsigned long long b2) {
  if (a1 >= b1) {
    unsigned long long cand = ((unsigned int)b1 == (unsigned int)a1) ? b2 : b1;
    if (cand > a2) a2 = cand;
  } else {
    unsigned long long n2 = ((unsigned int)a1 == (unsigned int)b1) ? a2 : a1;
    a2 = (n2 >= b2) ? n2 : b2;
    a1 = b1;
  }
}

// ============================================================================
// K0: embeddings -> combined[:,0:10]; e_t chunk-major
// ============================================================================
__global__ void k0_embed(const int* __restrict__ ib, const float* __restrict__ emb,
                         const float* __restrict__ Wih, const float* __restrict__ bih) {
  int t = blockIdx.x * blockDim.x + threadIdx.x;
  if (t >= T_LEN) return;
  int ix = ib[t];
  float w[EMB];
#pragma unroll
  for (int k = 0; k < EMB; k++) {
    w[k] = emb[ix * EMB + k];
    g_comb[t * CDIM + k] = w[k];
  }
  int c = t / CHL, j = t % CHL;
  float* e = &g_ecm[(j * NCHUNK + c) * HID];
#pragma unroll
  for (int i = 0; i < HID; i++) {
    float s = bih[i];
#pragma unroll
    for (int k = 0; k < EMB; k++) s += Wih[i * CDIM + k] * w[k];
    e[i] = s;
  }
}

// ============================================================================
// K1: per-chunk partial scan from h=0
// ============================================================================
__global__ void k1_chunkv(const float* __restrict__ Wih) {
  int c = blockIdx.x * blockDim.x + threadIdx.x;
  float A[HID][HID];
#pragma unroll
  for (int i = 0; i < HID; i++)
#pragma unroll
    for (int k = 0; k < HID; k++) A[i][k] = Wih[i * CDIM + EMB + k];
  float h[HID];
#pragma unroll
  for (int i = 0; i < HID; i++) h[i] = 0.f;
#pragma unroll
  for (int j = 0; j < CHL; j++) {
    const float* e = &g_ecm[(j * NCHUNK + c) * HID];
    float hn[HID];
#pragma unroll
    for (int i = 0; i < HID; i++) {
      float s = e[i];
#pragma unroll
      for (int k = 0; k < HID; k++) s += A[i][k] * h[k];
      hn[i] = s;
    }
#pragma unroll
    for (int i = 0; i < HID; i++) h[i] = hn[i];
  }
#pragma unroll
  for (int i = 0; i < HID; i++) g_v[c * HID + i] = h[i];
}

// ============================================================================
// K2: two-level chunk scan (M8=A^8, M256=M8^32) -> g_hs
// ============================================================================
__global__ void k2_scan(const float* __restrict__ Wih) {
  __shared__ float sM8[100], sM256[100], sT[100];
  __shared__ float sV[NCHUNK * 11];
  __shared__ float sgp[NGRP * 10], sge[NGRP * 10];
  int tid = threadIdx.x;

  if (tid < 100) sM8[tid] = Wih[(tid / 10) * CDIM + EMB + (tid % 10)];
  __syncthreads();
  for (int s = 0; s < 3; s++) {
    float acc = 0.f;
    if (tid < 100) {
      int i = tid / 10, k = tid % 10;
#pragma unroll
      for (int j = 0; j < 10; j++) acc += sM8[i * 10 + j] * sM8[j * 10 + k];
    }
    __syncthreads();
    if (tid < 100) sT[tid] = acc;
    __syncthreads();
    if (tid < 100) sM8[tid] = sT[tid];
    __syncthreads();
  }
  if (tid < 100) sM256[tid] = sM8[tid];
  __syncthreads();
  for (int s = 0; s < 5; s++) {
    float acc = 0.f;
    if (tid < 100) {
      int i = tid / 10, k = tid % 10;
#pragma unroll
      for (int j = 0; j < 10; j++) acc += sM256[i * 10 + j] * sM256[j * 10 + k];
    }
    __syncthreads();
    if (tid < 100) sT[tid] = acc;
    __syncthreads();
    if (tid < 100) sM256[tid] = sT[tid];
    __syncthreads();
  }
  for (int idx = tid; idx < NCHUNK * HID; idx += blockDim.x) {
    int ch = idx / HID, i = idx % HID;
    int g = ch / 32, c = ch % 32;
    sV[(c * 32 + g) * 11 + i] = g_v[idx];
  }
  __syncthreads();
  if (tid < NGRP) {
    float h[HID];
#pragma unroll
    for (int i = 0; i < HID; i++) h[i] = 0.f;
    for (int c = 0; c < 32; c++) {
      const float* v = &sV[(c * 32 + tid) * 11];
      float hn[HID];
#pragma unroll
      for (int i = 0; i < HID; i++) {
        float s = v[i];
#pragma unroll
        for (int k = 0; k < HID; k++) s += sM8[i * 10 + k] * h[k];
        hn[i] = s;
      }
#pragma unroll
      for (int i = 0; i < HID; i++) h[i] = hn[i];
    }
#pragma unroll
    for (int i = 0; i < HID; i++) sgp[tid * 10 + i] = h[i];
  }
  __syncthreads();
  if (tid == 0) {
    float h[HID];
#pragma unroll
    for (int i = 0; i < HID; i++) h[i] = 0.f;
    for (int g = 0; g < NGRP; g++) {
#pragma unroll
      for (int i = 0; i < HID; i++) sge[g * 10 + i] = h[i];
      float hn[HID];
#pragma unroll
      for (int i = 0; i < HID; i++) {
        float s = sgp[g * 10 + i];
#pragma unroll
        for (int k = 0; k < HID; k++) s += sM256[i * 10 + k] * h[k];
        hn[i] = s;
      }
#pragma unroll
      for (int i = 0; i < HID; i++) h[i] = hn[i];
    }
  }
  __syncthreads();
  if (tid < NGRP) {
    float h[HID];
#pragma unroll
    for (int i = 0; i < HID; i++) h[i] = sge[tid * 10 + i];
    for (int c = 0; c < 32; c++) {
      int ch = tid * 32 + c;
#pragma unroll
      for (int i = 0; i < HID; i++) g_hs[ch * HID + i] = h[i];
      const float* v = &sV[(c * 32 + tid) * 11];
      float hn[HID];
#pragma unroll
      for (int i = 0; i < HID; i++) {
        float s = v[i];
#pragma unroll
        for (int k = 0; k < HID; k++) s += sM8[i * 10 + k] * h[k];
        hn[i] = s;
      }
#pragma unroll
      for (int i = 0; i < HID; i++) h[i] = hn[i];
    }
  }
}

// ============================================================================
// K3: replay chunks -> h chunk-major
// ============================================================================
__global__ void k3_fill(const float* __restrict__ Wih) {
  int c = blockIdx.x * blockDim.x + threadIdx.x;
  float A[HID][HID];
#pragma unroll
  for (int i = 0; i < HID; i++)
#pragma unroll
    for (int k = 0; k < HID; k++) A[i][k] = Wih[i * CDIM + EMB + k];
  float h[HID];
#pragma unroll
  for (int i = 0; i < HID; i++) h[i] = g_hs[c * HID + i];
#pragma unroll
  for (int j = 0; j < CHL; j++) {
    const float* e = &g_ecm[(j * NCHUNK + c) * HID];
    float* ho = &g_hcm[(j * NCHUNK + c) * HID];
    float hn[HID];
#pragma unroll
    for (int i = 0; i < HID; i++) {
      ho[i] = h[i];
      float s = e[i];
#pragma unroll
      for (int k = 0; k < HID; k++) s += A[i][k] * h[k];
      hn[i] = s;
    }
#pragma unroll
    for (int i = 0; i < HID; i++) h[i] = hn[i];
  }
}

// ============================================================================
// K4: transpose h chunk-major -> g_comb[:,10:20]
// ============================================================================
__global__ void k4_transpose() {
  int idx = blockIdx.x * blockDim.x + threadIdx.x;
  if (idx >= T_LEN * HID) return;
  int j = idx / (NCHUNK * HID);
  int r = idx % (NCHUNK * HID);
  int c = r / HID, i = r % HID;
  int t = c * CHL + j;
  g_comb[t * CDIM + EMB + i] = g_hcm[idx];
}

// ============================================================================
// B prep: one thread per output u32, fully coalesced stores.
// Row layout (u32 p, k=2p): [0,10): hi | [10,20): hi | [20,30): lo |
//   p=30: (b_hi, b_lo) | p=31: 0
// ============================================================================
__global__ void k_bprep(const float* __restrict__ Wio, const float* __restrict__ bio) {
  int g = blockIdx.x * blockDim.x + threadIdx.x;
  if (g >= VOCAB * 32) return;
  int n = g >> 5, p = g & 31;
  unsigned int u = 0;
  if (p < 30) {
    int q = (p < 10) ? p : ((p < 20) ? p - 10 : p - 20);
    float x0 = Wio[n * CDIM + 2 * q], x1 = Wio[n * CDIM + 2 * q + 1];
    unsigned short a0, b0, a1, b1;
    split2(x0, a0, b0);
    split2(x1, a1, b1);
    u = (p < 20) ? ((unsigned int)a0 | ((unsigned int)a1 << 16))
                 : ((unsigned int)b0 | ((unsigned int)b1 << 16));
  } else if (p == 30) {
    unsigned short bh, bl;
    split2(bio[n], bh, bl);
    u = (unsigned int)bh | ((unsigned int)bl << 16);
  }
  g_bext[g] = u;
}

// ============================================================================
// A prep: j[0,10): hi | j[10,20): lo | j[20,30): hi | j=30: (1,1) | j=31: 0
// Fragment order: u32 idx = (t>>5)*1024 + mf*512 + ks*128 + lane*4 + r
// ============================================================================
__global__ void k_aprep() {
  int t = blockIdx.x * blockDim.x + threadIdx.x;
  if (t >= T_LEN) return;
  unsigned short hi[CDIM], lo[CDIM];
#pragma unroll
  for (int i = 0; i < CDIM; i++) split2(g_comb[t * CDIM + i], hi[i], lo[i]);
  const unsigned short one = 0x3C00;  // fp16(1.0)
  unsigned int base = (t >> 5) * 1024 + ((t >> 4) & 1) * 512;
  int rowlo = (t >> 3) & 1;
  int lhi = (t & 7) * 4;
#pragma unroll
  for (int j = 0; j < 32; j++) {
    unsigned short v0 = 0, v1 = 0;
    if (j < 10)       { v0 = hi[2 * j];        v1 = hi[2 * j + 1]; }
    else if (j < 20)  { v0 = lo[2 * (j - 10)]; v1 = lo[2 * (j - 10) + 1]; }
    else if (j < 30)  { v0 = hi[2 * (j - 20)]; v1 = hi[2 * (j - 20) + 1]; }
    else if (j == 30) { v0 = one; v1 = one; }
    unsigned int u = (unsigned int)v0 | ((unsigned int)v1 << 16);
    int ks = j >> 3;
    int lane = lhi + (j & 3);
    int r = ((j >> 2) & 1) * 2 + rowlo;
    g_aext[base + ks * 128 + lane * 4 + r] = u;
  }
}

// ============================================================================
// K5: fp16 mma.sync GEMM (K=64), 2 chunks/stage, 2 CTAs/SM, top-2 epilogue.
//   CTA: 256 thr = 8 warps, 256-row m slab; grid = 32 mCTAs x 8 ngroups.
// ============================================================================
__global__ void __launch_bounds__(256, 2) k5_mma() {
  __shared__ __align__(16) char sB[2][64 * BROW_PAD];   // 2 x 9216 B
  int tid = threadIdx.x, w = tid >> 5, lane = tid & 31;
  int ctam = blockIdx.x >> 3, ngrp = blockIdx.x & 7;
  int sw = ctam * 8 + w;

  // A fragments: 8 x uint4 per thread
  uint4 afr[4][2];
  {
    const uint4* ab = reinterpret_cast<const uint4*>(&g_aext[sw * 1024]);
#pragma unroll
    for (int mf = 0; mf < 2; mf++)
#pragma unroll
      for (int ks = 0; ks < 4; ks++) afr[ks][mf] = ab[(mf * 4 + ks) * 32 + lane];
  }

  float rv1[4], rv2[4];
  int rc1[4], rc2[4];
#pragma unroll
  for (int i = 0; i < 4; i++) { rv1[i] = -3.4e38f; rv2[i] = -3.4e38f; rc1[i] = 0; rc2[i] = 0; }

  const uint4* bg0 = reinterpret_cast<const uint4*>(&g_bext[(size_t)(ngrp * CH_PER_G) * 32 * 32]);
  // stage 0: 2 chunks = 512 uint4; element e -> row e>>3, col (e&7)*16
  uint4 pf0 = bg0[tid], pf1 = bg0[tid + 256];
  {
    int e0 = tid, e1 = tid + 256;
    *reinterpret_cast<uint4*>(&sB[0][(e0 >> 3) * BROW_PAD + (e0 & 7) * 16]) = pf0;
    *reinterpret_cast<uint4*>(&sB[0][(e1 >> 3) * BROW_PAD + (e1 & 7) * 16]) = pf1;
  }
  __syncthreads();

  int grp = lane >> 3, lr = lane & 7;
  for (int s2 = 0; s2 < STAGES; s2++) {
    if (s2 + 1 < STAGES) {
      pf0 = bg0[(size_t)(s2 + 1) * 512 + tid];
      pf1 = bg0[(size_t)(s2 + 1) * 512 + tid + 256];
    }
    uint32_t sbase = smem_u32(&sB[s2 & 1][0]);
#pragma unroll
    for (int sub = 0; sub < 2; sub++) {
      uint32_t sb0 = sbase + sub * 32 * BROW_PAD;
      float C[2][4][4];
#pragma unroll
      for (int mf = 0; mf < 2; mf++)
#pragma unroll
        for (int nf = 0; nf < 4; nf++)
#pragma unroll
          for (int i = 0; i < 4; i++) C[mf][nf][i] = 0.f;

#pragma unroll
      for (int ks = 0; ks < 4; ks++) {
        unsigned int bb[4][2];
#pragma unroll
        for (int p = 0; p < 2; p++) {
          uint32_t addr = sb0 + (p * 16 + (grp & 1) * 8 + lr) * BROW_PAD +
                          ((grp >> 1) << 4) + ks * 32;
          unsigned int r0, r1, r2, r3;
          asm volatile(
              "ldmatrix.sync.aligned.m8n8.x4.shared.b16 {%0,%1,%2,%3}, [%4];"
              : "=r"(r0), "=r"(r1), "=r"(r2), "=r"(r3) : "r"(addr));
          bb[2 * p][0] = r0; bb[2 * p + 1][0] = r1;
          bb[2 * p][1] = r2; bb[2 * p + 1][1] = r3;
        }
#pragma unroll
        for (int nf = 0; nf < 4; nf++)
#pragma unroll
          for (int mf = 0; mf < 2; mf++) {
            asm volatile(
                "mma.sync.aligned.m16n8k16.row.col.f32.f16.f16.f32 "
                "{%0,%1,%2,%3}, {%4,%5,%6,%7}, {%8,%9}, {%0,%1,%2,%3};"
                : "+f"(C[mf][nf][0]), "+f"(C[mf][nf][1]),
                  "+f"(C[mf][nf][2]), "+f"(C[mf][nf][3])
                : "r"(afr[ks][mf].x), "r"(afr[ks][mf].y),
                  "r"(afr[ks][mf].z), "r"(afr[ks][mf].w),
                  "r"(bb[nf][0]), "r"(bb[nf][1]));
          }
      }
      // epilogue: per-row chunk max, maintain top-2 distinct chunks
      int gch = ngrp * CH_PER_G + s2 * 2 + sub;
#pragma unroll
      for (int i = 0; i < 4; i++) {
        int mf = i >> 1, hb = i & 1;
        float m0 = fmaxf(C[mf][0][hb * 2], C[mf][0][hb * 2 + 1]);
        float m1 = fmaxf(C[mf][1][hb * 2], C[mf][1][hb * 2 + 1]);
        float m2 = fmaxf(C[mf][2][hb * 2], C[mf][2][hb * 2 + 1]);
        float m3 = fmaxf(C[mf][3][hb * 2], C[mf][3][hb * 2 + 1]);
        float m8 = fmaxf(fmaxf(m0, m1), fmaxf(m2, m3));
        if (m8 > rv1[i]) {
          rv2[i] = rv1[i]; rc2[i] = rc1[i];
          rv1[i] = m8; rc1[i] = gch;
        } else if (m8 > rv2[i]) {
          rv2[i] = m8; rc2[i] = gch;
        }
      }
    }
    // stage next 2 chunks
    if (s2 + 1 < STAGES) {
      char* nb = sB[(s2 + 1) & 1];
      int e0 = tid, e1 = tid + 256;
      *reinterpret_cast<uint4*>(&nb[(e0 >> 3) * BROW_PAD + (e0 & 7) * 16]) = pf0;
      *reinterpret_cast<uint4*>(&nb[(e1 >> 3) * BROW_PAD + (e1 & 7) * 16]) = pf1;
    }
    __syncthreads();
  }

  // quad merge of top-2 candidates; plain stores (no atomics)
#pragma unroll
  for (int i = 0; i < 4; i++) {
    unsigned long long p1 = ((unsigned long long)okey(rv1[i]) << 32) | (unsigned int)rc1[i];
    unsigned long long p2 = ((unsigned long long)okey(rv2[i]) << 32) | (unsigned int)rc2[i];
#pragma unroll
    for (int off = 1; off <= 2; off <<= 1) {
      unsigned long long o1 = __shfl_xor_sync(0xffffffffu, p1, off);
      unsigned long long o2 = __shfl_xor_sync(0xffffffffu, p2, off);
      merge2(p1, p2, o1, o2);
    }
    if ((lane & 3) == 0) {
      int t = ctam * 256 + w * 32 + i * 8 + (lane >> 2);
      g_cand[t * 16 + ngrp * 2 + 0] = p1;
      g_cand[t * 16 + ngrp * 2 + 1] = p2;
    }
  }
}

// ============================================================================
// K7: rescue — exact fp32 argmax over 16 candidate chunks (512 rows) per t.
// ============================================================================
__global__ void k7_rescue(const float* __restrict__ Wio, const float* __restrict__ bio,
                          float* __restrict__ out) {
  int warp = (blockIdx.x * blockDim.x + threadIdx.x) >> 5;
  int lane = threadIdx.x & 31;
  if (warp >= T_LEN) return;
  int t = warp;
  float c[CDIM];
#pragma unroll
  for (int k = 0; k < CDIM; k++) c[k] = g_comb[t * CDIM + k];
  unsigned long long best = 0ULL;
#pragma unroll
  for (int ci = 0; ci < 16; ci++) {
    unsigned int chunk = (unsigned int)g_cand[t * 16 + ci];
    int n = chunk * 32 + lane;
    float s = bio[n];
    const float* wr = &Wio[n * CDIM];
#pragma unroll
    for (int k = 0; k < CDIM; k++) s += wr[k] * c[k];
    unsigned long long pk = ((unsigned long long)okey(s) << 32) |
                            (unsigned int)(~(unsigned int)n);
    if (pk > best) best = pk;
  }
#pragma unroll
  for (int off = 16; off; off >>= 1) {
    unsigned long long o = __shfl_down_sync(0xffffffffu, best, off);
    if (o > best) best = o;
  }
  if (lane == 0) out[t] = (float)(~(unsigned int)best);
}

extern "C" void kernel_launch(void* const* d_in, const int* in_sizes, int n_in,
                              void* d_out, int out_size) {
  const int*   ib  = (const int*)d_in[0];
  const float* emb = (const float*)d_in[1];
  const float* Wih = (const float*)d_in[2];
  const float* bih = (const float*)d_in[3];
  const float* Wio = (const float*)d_in[4];
  const float* bio = (const float*)d_in[5];
  float* out = (float*)d_out;

  k_bprep<<<(VOCAB * 32) / 256, 256>>>(Wio, bio);
  k0_embed<<<T_LEN / 128, 128>>>(ib, emb, Wih, bih);
  k1_chunkv<<<NCHUNK / 128, 128>>>(Wih);
  k2_scan<<<1, 128>>>(Wih);
  k3_fill<<<NCHUNK / 128, 128>>>(Wih);
  k4_transpose<<<(T_LEN * HID + 127) / 128, 128>>>();
  k_aprep<<<T_LEN / 128, 128>>>();
  k5_mma<<<MCTA * NG, 256>>>();
  k7_rescue<<<T_LEN / 8, 256>>>(Wio, bio, out);
}